// round 1
// baseline (speedup 1.0000x reference)
#include <cuda_runtime.h>
#include <cuda_bf16.h>
#include <cstdint>

// ---------------- problem constants ----------------
#define BATCH 32
#define NTOK  4096
#define FEAT  768
#define DIM   256
#define KVQ   256
#define NHEAD 4
#define DH    64
#define KSLOT 16
#define CHAN  64            // KSLOT * NHEAD
#define ITERS 3
#define EPSW  1e-8f
#define SCALE 0.125f        // DH^-0.5
#define MROWS (BATCH*NTOK)  // 131072

// ---------------- scratch (device globals; no allocation allowed) ----------------
__device__ float g_mean[MROWS];
__device__ float g_rstd[MROWS];
__device__ float g_wkv [768*512];     // [k][n] transposed+concat k|v proj weights
__device__ float g_wqt [256*256];     // [c][o]
__device__ float g_wih_t[256*768];    // [c][row]
__device__ float g_whh_t[256*768];
__device__ float g_wf1t[256*1024];    // [c][row]
__device__ float g_wf2t[1024*256];    // [j][t]
__device__ float g_kv  [(size_t)MROWS*512];   // per token: k[0:256] | v[256:512]
__device__ float g_q   [BATCH*KSLOT*256];
__device__ float g_slots[BATCH*KSLOT*256];
__device__ float g_vsp [BATCH*16*256];
__device__ float g_vsum[BATCH*256];
__device__ float g_Apart[BATCH*16*CHAN*DH];   // [b][split][c][d]
__device__ float g_Spart[BATCH*16*CHAN];

// ---------------- helpers ----------------
__device__ __forceinline__ float2 blockReduce2(float a, float b, float* sh) {
    __syncthreads();
    #pragma unroll
    for (int off = 16; off; off >>= 1) {
        a += __shfl_xor_sync(0xffffffffu, a, off);
        b += __shfl_xor_sync(0xffffffffu, b, off);
    }
    int wid = threadIdx.x >> 5, lane = threadIdx.x & 31;
    if (lane == 0) { sh[wid*2] = a; sh[wid*2+1] = b; }
    __syncthreads();
    float ra = 0.f, rb = 0.f;
    #pragma unroll
    for (int w = 0; w < 8; w++) { ra += sh[w*2]; rb += sh[w*2+1]; }
    return make_float2(ra, rb);
}

__device__ __forceinline__ float sigmoidf_(float x) { return 1.0f / (1.0f + __expf(-x)); }
__device__ __forceinline__ float gelu_exact(float x) { return 0.5f * x * (1.0f + erff(x * 0.70710678118654752f)); }

// ---------------- prep: weight transposes + slots init ----------------
__global__ void prep_kernel(const float* __restrict__ kw, const float* __restrict__ vw,
                            const float* __restrict__ wih, const float* __restrict__ whh,
                            const float* __restrict__ f1, const float* __restrict__ f2,
                            const float* __restrict__ qw, const float* __restrict__ cond) {
    int idx = blockIdx.x * blockDim.x + threadIdx.x;
    int stride = gridDim.x * blockDim.x;
    for (int p = idx; p < 768*512; p += stride) {
        int k = p >> 9, n = p & 511;
        g_wkv[p] = (n < 256) ? kw[n*768 + k] : vw[(n-256)*768 + k];
    }
    for (int p = idx; p < 256*768; p += stride) {
        int c = p / 768, r = p - c*768;
        g_wih_t[p] = wih[r*256 + c];
        g_whh_t[p] = whh[r*256 + c];
    }
    for (int p = idx; p < 256*1024; p += stride) {
        g_wf1t[p] = f1[(p & 1023)*256 + (p >> 10)];
    }
    for (int p = idx; p < 1024*256; p += stride) {
        g_wf2t[p] = f2[(p & 255)*1024 + (p >> 8)];
    }
    for (int p = idx; p < 256*256; p += stride) {
        g_wqt[p] = qw[(p & 255)*256 + (p >> 8)];
    }
    for (int p = idx; p < BATCH*KSLOT*256; p += stride) g_slots[p] = cond[p];
}

// ---------------- row stats for input LN ----------------
__global__ __launch_bounds__(256) void stats_kernel(const float* __restrict__ x) {
    __shared__ float sh[16];
    size_t row = blockIdx.x;
    const float* xr = x + row * FEAT;
    int t = threadIdx.x;
    float v0 = xr[t], v1 = xr[t+256], v2 = xr[t+512];
    float s = v0+v1+v2, s2 = v0*v0 + v1*v1 + v2*v2;
    float2 r = blockReduce2(s, s2, sh);
    if (t == 0) {
        float m = r.x * (1.0f/768.0f);
        float var = r.y * (1.0f/768.0f) - m*m;
        g_mean[row] = m;
        g_rstd[row] = rsqrtf(var + 1e-5f);
    }
}

// ---------------- fused LN + k|v projection GEMM ----------------
#define BM 128
#define BN 64
#define BK 16
__global__ __launch_bounds__(256) void gemm_kv(const float* __restrict__ x,
                                               const float* __restrict__ lng,
                                               const float* __restrict__ lnb) {
    __shared__ float As[BK][BM + 4];
    __shared__ float Bs[BK][BN];
    int tid = threadIdx.x;
    int tx = tid & 15, ty = tid >> 4;
    int bm0 = blockIdx.y * BM;
    int bn0 = blockIdx.x * BN;
    float acc[8][4] = {};
    for (int k0 = 0; k0 < FEAT; k0 += BK) {
        // A tile: 128 rows x 16 cols, fused LN. 512 float4, 2/thread.
        #pragma unroll
        for (int it = 0; it < 2; it++) {
            int idx = tid + it*256;
            int row = idx >> 2, kq = idx & 3;
            int rowG = bm0 + row;
            float4 xv = *(const float4*)(x + (size_t)rowG*FEAT + k0 + kq*4);
            float m = g_mean[rowG], rs = g_rstd[rowG];
            float4 gv = *(const float4*)(lng + k0 + kq*4);
            float4 bv = *(const float4*)(lnb + k0 + kq*4);
            As[kq*4+0][row] = (xv.x - m)*rs*gv.x + bv.x;
            As[kq*4+1][row] = (xv.y - m)*rs*gv.y + bv.y;
            As[kq*4+2][row] = (xv.z - m)*rs*gv.z + bv.z;
            As[kq*4+3][row] = (xv.w - m)*rs*gv.w + bv.w;
        }
        // B tile: 16 x 64 = 256 float4, 1/thread
        {
            int kr = tid >> 4, nq = tid & 15;
            *(float4*)&Bs[kr][nq*4] = *(const float4*)(g_wkv + (size_t)(k0+kr)*512 + bn0 + nq*4);
        }
        __syncthreads();
        #pragma unroll
        for (int k = 0; k < BK; k++) {
            float4 a0 = *(const float4*)&As[k][ty*8];
            float4 a1 = *(const float4*)&As[k][ty*8+4];
            float4 bv = *(const float4*)&Bs[k][tx*4];
            float av[8] = {a0.x,a0.y,a0.z,a0.w,a1.x,a1.y,a1.z,a1.w};
            float bb[4] = {bv.x,bv.y,bv.z,bv.w};
            #pragma unroll
            for (int i = 0; i < 8; i++)
                #pragma unroll
                for (int j = 0; j < 4; j++)
                    acc[i][j] += av[i]*bb[j];
        }
        __syncthreads();
    }
    #pragma unroll
    for (int i = 0; i < 8; i++) {
        int row = bm0 + ty*8 + i;
        float4 o = make_float4(acc[i][0], acc[i][1], acc[i][2], acc[i][3]);
        *(float4*)(g_kv + (size_t)row*512 + bn0 + tx*4) = o;
    }
}

// ---------------- vsum = sum_j v[b,j,:] ----------------
__global__ __launch_bounds__(256) void vsum_part_kernel() {
    int b = blockIdx.y, sp = blockIdx.x;
    int t = threadIdx.x;
    float s = 0.f;
    int j0 = sp * 256;
    for (int j = 0; j < 256; j++)
        s += g_kv[((size_t)(b*NTOK + j0 + j))*512 + 256 + t];
    g_vsp[(b*16+sp)*256 + t] = s;
}
__global__ __launch_bounds__(256) void vsum_reduce_kernel() {
    int b = blockIdx.x, t = threadIdx.x;
    float s = 0.f;
    for (int sp = 0; sp < 16; sp++) s += g_vsp[(b*16+sp)*256 + t];
    g_vsum[b*256 + t] = s;
}

// ---------------- slot LN + q projection ----------------
__global__ __launch_bounds__(256) void qproj_kernel(const float* __restrict__ lng,
                                                    const float* __restrict__ lnb) {
    __shared__ float s_ln[256];
    __shared__ float sh[16];
    int t = threadIdx.x;
    int bi = blockIdx.x;
    float xv = g_slots[(size_t)bi*256 + t];
    float2 r = blockReduce2(xv, xv*xv, sh);
    float m = r.x * (1.0f/256.0f);
    float var = r.y * (1.0f/256.0f) - m*m;
    float rs = rsqrtf(var + 1e-5f);
    s_ln[t] = (xv - m)*rs*lng[t] + lnb[t];
    __syncthreads();
    float acc = 0.f;
    for (int c = 0; c < 256; c++) acc += s_ln[c] * g_wqt[c*256 + t];
    g_q[(size_t)bi*256 + t] = acc;
}

// ---------------- attention pass ----------------
// padded smem layouts: each 16-float group padded to 20 floats (conflict-free LDS.128)
#define QS_CSTRIDE 80     // 4 groups * 20
#define KV_RSTRIDE 320    // 16 groups * 20
__global__ __launch_bounds__(256) void attn_kernel(float* __restrict__ attn_out, int lastIter) {
    __shared__ float qs[CHAN * QS_CSTRIDE];   // 20KB
    __shared__ float ks[8][KV_RSTRIDE];       // 10KB
    __shared__ float vs[8][KV_RSTRIDE];       // 10KB
    __shared__ float wsum[8][8];
    int b = blockIdx.y, sp = blockIdx.x;
    int tid = threadIdx.x;
    // load q: q[b, c, d] contiguous (4096 floats) -> padded layout
    #pragma unroll
    for (int it = 0; it < 4; it++) {
        int idx = tid + it*256;             // float4 index, 0..1023
        int dlin = idx * 4;
        int c = dlin >> 6, rem = dlin & 63;
        int grp = rem >> 4, within = rem & 15;
        float4 v4 = *(const float4*)(g_q + (size_t)b*4096 + dlin);
        *(float4*)&qs[c*QS_CSTRIDE + grp*20 + within] = v4;
    }
    int c = tid >> 2, qd = tid & 3, h = c & 3;
    int grpIdx = h*4 + qd;                  // 16-float group within 256
    float accA[16] = {};
    float accS = 0.f;
    int lane = tid & 31, wid = tid >> 5;
    int j0base = sp * 256;

    for (int ch = 0; ch < 32; ch++) {
        __syncthreads();
        int j0 = j0base + ch*8;
        // load 8 tokens of kv (8 x 512 floats = 1024 float4)
        #pragma unroll
        for (int it = 0; it < 4; it++) {
            int idx = tid + it*256;
            int r = idx >> 7, w = idx & 127;   // w: float4 within 512 floats
            float4 v4 = *(const float4*)(g_kv + ((size_t)(b*NTOK + j0 + r))*512 + w*4);
            int g16 = (w >> 2) & 15;           // group within k or v half
            int off = g16*20 + (w & 3)*4;
            if (w < 64) *(float4*)&ks[r][off] = v4;
            else        *(float4*)&vs[r][off] = v4;
        }
        __syncthreads();
        float e[8];
        #pragma unroll
        for (int r = 0; r < 8; r++) {
            const float* qp = &qs[c*QS_CSTRIDE + qd*20];
            const float* kp = &ks[r][grpIdx*20];
            float pd = 0.f;
            #pragma unroll
            for (int dd = 0; dd < 16; dd += 4) {
                float4 qa = *(const float4*)(qp + dd);
                float4 ka = *(const float4*)(kp + dd);
                pd += qa.x*ka.x + qa.y*ka.y + qa.z*ka.z + qa.w*ka.w;
            }
            pd += __shfl_xor_sync(0xffffffffu, pd, 1);
            pd += __shfl_xor_sync(0xffffffffu, pd, 2);
            float ev = __expf(pd * SCALE);
            e[r] = ev;
            float val = (qd == 0) ? ev : 0.f;
            #pragma unroll
            for (int off = 16; off; off >>= 1) val += __shfl_xor_sync(0xffffffffu, val, off);
            if (lane == 0) wsum[wid][r] = val;
        }
        __syncthreads();
        #pragma unroll
        for (int r = 0; r < 8; r++) {
            float tot = 0.f;
            #pragma unroll
            for (int w = 0; w < 8; w++) tot += wsum[w][r];
            float attn = e[r] / tot;
            accS += attn;
            const float* vp = &vs[r][grpIdx*20];
            #pragma unroll
            for (int dd = 0; dd < 16; dd += 4) {
                float4 va = *(const float4*)(vp + dd);
                accA[dd+0] += attn * va.x;
                accA[dd+1] += attn * va.y;
                accA[dd+2] += attn * va.z;
                accA[dd+3] += attn * va.w;
            }
            if (lastIter) {
                float shv = attn + __shfl_xor_sync(0xffffffffu, attn, 4);
                shv += __shfl_xor_sync(0xffffffffu, shv, 8);
                if ((tid & 15) == 0) {
                    int slot = tid >> 4;
                    attn_out[((size_t)(b*KSLOT + slot))*NTOK + j0 + r] = shv * 0.25f;
                }
            }
        }
    }
    // write partials
    size_t base = ((size_t)((b*16 + sp)*CHAN + c))*DH + qd*16;
    #pragma unroll
    for (int dd = 0; dd < 16; dd += 4)
        *(float4*)(g_Apart + base + dd) = make_float4(accA[dd], accA[dd+1], accA[dd+2], accA[dd+3]);
    if (qd == 0) g_Spart[(b*16 + sp)*CHAN + c] = accS;
}

// ---------------- update: normalize + GRU + FF, 4 slots per block ----------------
__global__ __launch_bounds__(256) void update_kernel(
        const float* __restrict__ gbih, const float* __restrict__ gbhh,
        const float* __restrict__ ffg, const float* __restrict__ ffb,
        const float* __restrict__ fb1, const float* __restrict__ fb2,
        float* __restrict__ out_slots, int last) {
    __shared__ float u4 [4][256];
    __shared__ float h4 [4][256];
    __shared__ float hn4[4][256];
    __shared__ float ln4[4][256];
    __shared__ float h1s[4][1024];
    __shared__ float sh[16];
    int t = threadIdx.x;
    int base = blockIdx.x * 4;
    int b = base >> 4;
    int hh = t >> 6, d = t & 63;
    // step 1: updates u = (A + eps*Vsum) / (S0 + N*eps); load hprev
    float vsm = g_vsum[b*256 + t];
    #pragma unroll
    for (int s = 0; s < 4; s++) {
        int i = (base + s) & 15;
        int c = i*NHEAD + hh;
        float A = 0.f, S0 = 0.f;
        #pragma unroll
        for (int sp = 0; sp < 16; sp++) {
            A  += g_Apart[((size_t)((b*16+sp)*CHAN + c))*DH + d];
            S0 += g_Spart[(b*16+sp)*CHAN + c];
        }
        float S = S0 + (float)NTOK * EPSW;
        u4[s][t] = (A + EPSW * vsm) / S;
        h4[s][t] = g_slots[(size_t)(base+s)*256 + t];
    }
    __syncthreads();
    // step 2: GRU gates (thread t owns gate rows t, 256+t, 512+t)
    float gir[4] = {}, giz[4] = {}, gin[4] = {};
    float ghr[4] = {}, ghz[4] = {}, ghn[4] = {};
    for (int cc = 0; cc < 256; cc++) {
        float wr = g_wih_t[cc*768 + t];
        float wz = g_wih_t[cc*768 + 256 + t];
        float wn = g_wih_t[cc*768 + 512 + t];
        float vr = g_whh_t[cc*768 + t];
        float vz = g_whh_t[cc*768 + 256 + t];
        float vn = g_whh_t[cc*768 + 512 + t];
        #pragma unroll
        for (int s = 0; s < 4; s++) {
            float xv = u4[s][cc], hv = h4[s][cc];
            gir[s] += wr*xv; giz[s] += wz*xv; gin[s] += wn*xv;
            ghr[s] += vr*hv; ghz[s] += vz*hv; ghn[s] += vn*hv;
        }
    }
    float bir = gbih[t], biz = gbih[256+t], bin = gbih[512+t];
    float bhr = gbhh[t], bhz = gbhh[256+t], bhn = gbhh[512+t];
    #pragma unroll
    for (int s = 0; s < 4; s++) {
        float r = sigmoidf_(gir[s] + bir + ghr[s] + bhr);
        float z = sigmoidf_(giz[s] + biz + ghz[s] + bhz);
        float n = tanhf(gin[s] + bin + r*(ghn[s] + bhn));
        hn4[s][t] = (1.0f - z)*n + z*h4[s][t];
    }
    __syncthreads();
    // step 3: LN per slot
    #pragma unroll
    for (int s = 0; s < 4; s++) {
        float v = hn4[s][t];
        float2 r = blockReduce2(v, v*v, sh);
        float m = r.x * (1.0f/256.0f);
        float var = r.y * (1.0f/256.0f) - m*m;
        float rs = rsqrtf(var + 1e-5f);
        ln4[s][t] = (v - m)*rs*ffg[t] + ffb[t];
    }
    __syncthreads();
    // step 4: FF1 + gelu
    float a1[4][4] = {};
    for (int cc = 0; cc < 256; cc++) {
        float w0 = g_wf1t[cc*1024 + t];
        float w1 = g_wf1t[cc*1024 + 256 + t];
        float w2 = g_wf1t[cc*1024 + 512 + t];
        float w3 = g_wf1t[cc*1024 + 768 + t];
        #pragma unroll
        for (int s = 0; s < 4; s++) {
            float xv = ln4[s][cc];
            a1[s][0] += w0*xv; a1[s][1] += w1*xv; a1[s][2] += w2*xv; a1[s][3] += w3*xv;
        }
    }
    #pragma unroll
    for (int s = 0; s < 4; s++) {
        #pragma unroll
        for (int q = 0; q < 4; q++) {
            int row = q*256 + t;
            h1s[s][row] = gelu_exact(a1[s][q] + fb1[row]);
        }
    }
    __syncthreads();
    // step 5: FF2 + residual
    float o[4];
    #pragma unroll
    for (int s = 0; s < 4; s++) o[s] = hn4[s][t] + fb2[t];
    for (int j = 0; j < 1024; j++) {
        float w = g_wf2t[j*256 + t];
        #pragma unroll
        for (int s = 0; s < 4; s++) o[s] += w * h1s[s][j];
    }
    #pragma unroll
    for (int s = 0; s < 4; s++) {
        g_slots[(size_t)(base+s)*256 + t] = o[s];
        if (last) out_slots[(size_t)(base+s)*256 + t] = o[s];
    }
}

// ---------------- launch ----------------
extern "C" void kernel_launch(void* const* d_in, const int* in_sizes, int n_in,
                              void* d_out, int out_size) {
    const float* inputs   = (const float*)d_in[0];
    const float* cond     = (const float*)d_in[1];
    const float* to_q_w   = (const float*)d_in[2];
    const float* to_k_w   = (const float*)d_in[3];
    const float* to_v_w   = (const float*)d_in[4];
    const float* gru_w_ih = (const float*)d_in[5];
    const float* gru_w_hh = (const float*)d_in[6];
    const float* gru_b_ih = (const float*)d_in[7];
    const float* gru_b_hh = (const float*)d_in[8];
    const float* ln_in_g  = (const float*)d_in[9];
    const float* ln_in_b  = (const float*)d_in[10];
    const float* ln_sl_g  = (const float*)d_in[11];
    const float* ln_sl_b  = (const float*)d_in[12];
    const float* ff_ln_g  = (const float*)d_in[13];
    const float* ff_ln_b  = (const float*)d_in[14];
    const float* ff_w1    = (const float*)d_in[15];
    const float* ff_b1    = (const float*)d_in[16];
    const float* ff_w2    = (const float*)d_in[17];
    const float* ff_b2    = (const float*)d_in[18];
    float* out = (float*)d_out;
    float* out_attn = out + BATCH*KSLOT*256;   // slots first, then attn_out

    prep_kernel<<<1024, 256>>>(to_k_w, to_v_w, gru_w_ih, gru_w_hh, ff_w1, ff_w2, to_q_w, cond);
    stats_kernel<<<MROWS, 256>>>(inputs);
    gemm_kv<<<dim3(512/BN, MROWS/BM), 256>>>(inputs, ln_in_g, ln_in_b);
    vsum_part_kernel<<<dim3(16, BATCH), 256>>>();
    vsum_reduce_kernel<<<BATCH, 256>>>();

    for (int it = 0; it < ITERS; it++) {
        int last = (it == ITERS - 1) ? 1 : 0;
        qproj_kernel<<<BATCH*KSLOT, 256>>>(ln_sl_g, ln_sl_b);
        attn_kernel<<<dim3(16, BATCH), 256>>>(out_attn, last);
        update_kernel<<<BATCH*KSLOT/4, 256>>>(gru_b_ih, gru_b_hh, ff_ln_g, ff_ln_b,
                                              ff_b1, ff_b2, out, last);
    }
}

// round 6
// speedup vs baseline: 1.6721x; 1.6721x over previous
#include <cuda_runtime.h>
#include <cuda_bf16.h>
#include <cstdint>

// ---------------- problem constants ----------------
#define BATCH 32
#define NTOK  4096
#define FEAT  768
#define DIM   256
#define KVQ   256
#define NHEAD 4
#define DH    64
#define KSLOT 16
#define CHAN  64            // KSLOT * NHEAD
#define ITERS 3
#define EPSW  1e-8f
#define SCALE 0.125f        // DH^-0.5
#define MROWS (BATCH*NTOK)  // 131072

// GEMM config (mma.sync bf16, 3-term split via K-concat)
#define GBM 128
#define GBN 64
#define GBK 64
#define KEFF 2304           // 768 hi*hi + 768 hi*lo + 768 lo*hi
#define KSTAGES (KEFF/GBK)  // 36

// ---------------- scratch (device globals; no allocation allowed) ----------------
__device__ __align__(16) __nv_bfloat16 g_a2[(size_t)MROWS*1536]; // [m][0:768)=hi, [768:1536)=lo (LN'd input)
__device__ __align__(16) __nv_bfloat16 g_b2[512*KEFF];           // [n][k]: k<768 hi, <1536 lo, <2304 hi
__device__ float g_wqt [256*256];     // [c][o]
__device__ float g_wih_t[256*768];    // [c][row]
__device__ float g_whh_t[256*768];
__device__ float g_wf1t[256*1024];    // [c][row]
__device__ float g_wf2t[1024*256];    // [j][t]
__device__ float g_kv  [(size_t)MROWS*512];   // per token: k[0:256] | v[256:512]
__device__ float g_q   [BATCH*KSLOT*256];
__device__ float g_slots[BATCH*KSLOT*256];
__device__ float g_vsp [BATCH*16*256];
__device__ float g_vsum[BATCH*256];
__device__ float g_Apart[BATCH*16*CHAN*DH];   // [b][split][c][d]
__device__ float g_Spart[BATCH*16*CHAN];

// ---------------- PTX helpers (base-target only: cp.async / ldmatrix / mma.sync) ----
__device__ __forceinline__ uint32_t smem_u32(const void* p) {
    uint32_t a;
    asm("{ .reg .u64 t; cvta.to.shared.u64 t, %1; cvt.u32.u64 %0, t; }" : "=r"(a) : "l"(p));
    return a;
}
#define SWZ128(off) ((off) ^ (((off) >> 3) & 0x70))
#define CP16(dst, src) asm volatile("cp.async.cg.shared.global [%0], [%1], 16;" :: "r"(dst), "l"(src))
#define CP_COMMIT()    asm volatile("cp.async.commit_group;" ::: "memory")
#define CP_WAIT0()     asm volatile("cp.async.wait_group 0;" ::: "memory")

#define LDSM4(R, addr) \
  asm volatile("ldmatrix.sync.aligned.m8n8.x4.shared.b16 {%0,%1,%2,%3}, [%4];" \
    : "=r"((R)[0]), "=r"((R)[1]), "=r"((R)[2]), "=r"((R)[3]) : "r"(addr))

#define MMA16816(C, A, B0, B1) \
  asm volatile("mma.sync.aligned.m16n8k16.row.col.f32.bf16.bf16.f32 " \
    "{%0,%1,%2,%3}, {%4,%5,%6,%7}, {%8,%9}, {%0,%1,%2,%3};" \
    : "+f"((C)[0]), "+f"((C)[1]), "+f"((C)[2]), "+f"((C)[3]) \
    : "r"((A)[0]), "r"((A)[1]), "r"((A)[2]), "r"((A)[3]), "r"(B0), "r"(B1))

// ---------------- generic helpers ----------------
__device__ __forceinline__ float2 blockReduce2(float a, float b, float* sh) {
    __syncthreads();
    #pragma unroll
    for (int off = 16; off; off >>= 1) {
        a += __shfl_xor_sync(0xffffffffu, a, off);
        b += __shfl_xor_sync(0xffffffffu, b, off);
    }
    int wid = threadIdx.x >> 5, lane = threadIdx.x & 31;
    if (lane == 0) { sh[wid*2] = a; sh[wid*2+1] = b; }
    __syncthreads();
    float ra = 0.f, rb = 0.f;
    #pragma unroll
    for (int w = 0; w < 8; w++) { ra += sh[w*2]; rb += sh[w*2+1]; }
    return make_float2(ra, rb);
}
__device__ __forceinline__ float sigmoidf_(float x) { return 1.0f / (1.0f + __expf(-x)); }
__device__ __forceinline__ float gelu_exact(float x) { return 0.5f * x * (1.0f + erff(x * 0.70710678118654752f)); }

// ---------------- prep: weight transposes + split-bf16 B + slots init ----------------
__global__ void prep_kernel(const float* __restrict__ kw, const float* __restrict__ vw,
                            const float* __restrict__ wih, const float* __restrict__ whh,
                            const float* __restrict__ f1, const float* __restrict__ f2,
                            const float* __restrict__ qw, const float* __restrict__ cond) {
    int idx = blockIdx.x * blockDim.x + threadIdx.x;
    int stride = gridDim.x * blockDim.x;
    for (int p = idx; p < 512*KEFF; p += stride) {
        int n = p / KEFF, kk = p - n*KEFF;
        int k = (kk < 768) ? kk : ((kk < 1536) ? kk - 768 : kk - 1536);
        float src = (n < 256) ? kw[n*768 + k] : vw[(n-256)*768 + k];
        __nv_bfloat16 h = __float2bfloat16(src);
        if (kk >= 768 && kk < 1536) h = __float2bfloat16(src - __bfloat162float(h));
        g_b2[p] = h;
    }
    for (int p = idx; p < 256*768; p += stride) {
        int c = p / 768, r = p - c*768;
        g_wih_t[p] = wih[r*256 + c];
        g_whh_t[p] = whh[r*256 + c];
    }
    for (int p = idx; p < 256*1024; p += stride) g_wf1t[p] = f1[(p & 1023)*256 + (p >> 10)];
    for (int p = idx; p < 1024*256; p += stride) g_wf2t[p] = f2[(p & 255)*1024 + (p >> 8)];
    for (int p = idx; p < 256*256; p += stride)  g_wqt[p]  = qw[(p & 255)*256 + (p >> 8)];
    for (int p = idx; p < BATCH*KSLOT*256; p += stride) g_slots[p] = cond[p];
}

// ---------------- fused LN + split-bf16 conversion of inputs ----------------
__global__ __launch_bounds__(256) void ln_convert_kernel(const float* __restrict__ x,
                                                         const float* __restrict__ lng,
                                                         const float* __restrict__ lnb) {
    __shared__ float sh[16];
    size_t row = blockIdx.x;
    const float* xr = x + row * FEAT;
    int t = threadIdx.x;
    float v0 = xr[t], v1 = xr[t+256], v2 = xr[t+512];
    float2 r = blockReduce2(v0+v1+v2, v0*v0 + v1*v1 + v2*v2, sh);
    float m = r.x * (1.0f/768.0f);
    float var = r.y * (1.0f/768.0f) - m*m;
    float rs = rsqrtf(var + 1e-5f);
    __nv_bfloat16* dst = g_a2 + row * 1536;
    float vv[3] = {v0, v1, v2};
    #pragma unroll
    for (int i = 0; i < 3; i++) {
        int col = t + i*256;
        float val = (vv[i] - m)*rs*lng[col] + lnb[col];
        __nv_bfloat16 hi = __float2bfloat16(val);
        __nv_bfloat16 lo = __float2bfloat16(val - __bfloat162float(hi));
        dst[col] = hi;
        dst[768 + col] = lo;
    }
}

// ---------------- k|v projection GEMM via mma.sync bf16 ----------------
// C[131072, 512] = A2 x B2^T, single K=2304 bf16 GEMM (3-term split).
// Segment pairing: kk in [0,768): A hi * B hi
//                  kk in [768,1536): A hi (ka=kk-768) * B lo
//                  kk in [1536,2304): A lo (ka=kk-768 -> [768,1536)) * B hi
__device__ __forceinline__ void gemm_load_stage(int tid, int m0, int bn0, int ks, char* sbuf) {
    int kk = ks * GBK;
    int ka = (kk < 768) ? kk : kk - 768;   // <- the R5 fix (was kk<1536 ? kk : kk-1536)
    uint32_t sA = smem_u32(sbuf);
    uint32_t sB = sA + 16384;
    #pragma unroll
    for (int i = 0; i < 4; i++) {
        int c = tid + i*256;
        int row = c >> 3, seg = c & 7;
        const char* src = (const char*)g_a2 + ((size_t)(m0+row)*1536 + ka)*2 + seg*16;
        CP16(sA + SWZ128((uint32_t)(row*128 + seg*16)), src);
    }
    #pragma unroll
    for (int i = 0; i < 2; i++) {
        int c = tid + i*256;
        int row = c >> 3, seg = c & 7;
        const char* src = (const char*)g_b2 + ((size_t)(bn0+row)*KEFF + kk)*2 + seg*16;
        CP16(sB + SWZ128((uint32_t)(row*128 + seg*16)), src);
    }
}

__global__ __launch_bounds__(256) void gemm_kv_mma() {
    __shared__ __align__(1024) char smem[2][24576];  // per stage: A 16KB (128x128B) + B 8KB (64x128B)
    const int tid = threadIdx.x;
    const int wid = tid >> 5, lane = tid & 31;
    const int m0  = blockIdx.y * GBM;
    const int bn0 = blockIdx.x * GBN;
    const int wm = wid >> 1, wn = wid & 1;   // warp tile: 32x32 at (wm*32, wn*32)

    float acc[2][4][4];
    #pragma unroll
    for (int a = 0; a < 2; a++)
        #pragma unroll
        for (int b = 0; b < 4; b++)
            #pragma unroll
            for (int c = 0; c < 4; c++) acc[a][b][c] = 0.f;

    gemm_load_stage(tid, m0, bn0, 0, smem[0]);
    CP_COMMIT();

    // precomputed ldmatrix lane addressing
    const int a_row = wm*32 + (lane & 15);
    const int a_col = (lane >> 4) << 4;           // 0 or 16 bytes
    const int b_g = lane >> 3, b_r = lane & 7;
    const int b_row = wn*32 + ((b_g >> 1) << 3) + b_r;
    const int b_col = (b_g & 1) << 4;

    for (int ks = 0; ks < KSTAGES; ks++) {
        CP_WAIT0();
        __syncthreads();
        if (ks + 1 < KSTAGES) {
            gemm_load_stage(tid, m0, bn0, ks + 1, smem[(ks + 1) & 1]);
            CP_COMMIT();
        }
        uint32_t sA = smem_u32(smem[ks & 1]);
        uint32_t sB = sA + 16384;
        #pragma unroll
        for (int k16 = 0; k16 < 4; k16++) {
            uint32_t afr[2][4], bfr[2][4];
            #pragma unroll
            for (int mt = 0; mt < 2; mt++) {
                uint32_t addr = sA + SWZ128((uint32_t)((a_row + mt*16)*128 + k16*32 + a_col));
                LDSM4(afr[mt], addr);
            }
            #pragma unroll
            for (int p = 0; p < 2; p++) {
                uint32_t addr = sB + SWZ128((uint32_t)((b_row + p*16)*128 + k16*32 + b_col));
                LDSM4(bfr[p], addr);
            }
            #pragma unroll
            for (int mt = 0; mt < 2; mt++)
                #pragma unroll
                for (int nt = 0; nt < 4; nt++) {
                    int p = nt >> 1, h = nt & 1;
                    MMA16816(acc[mt][nt], afr[mt], bfr[p][h*2], bfr[p][h*2+1]);
                }
        }
        __syncthreads();
    }

    // epilogue: fp32 accumulators -> g_kv
    int quad = lane >> 2, qid = lane & 3;
    #pragma unroll
    for (int mt = 0; mt < 2; mt++)
        #pragma unroll
        for (int nt = 0; nt < 4; nt++) {
            int mrow = m0 + wm*32 + mt*16 + quad;
            int col  = bn0 + wn*32 + nt*8 + qid*2;
            *(float2*)(g_kv + (size_t)mrow*512 + col)     = make_float2(acc[mt][nt][0], acc[mt][nt][1]);
            *(float2*)(g_kv + (size_t)(mrow+8)*512 + col) = make_float2(acc[mt][nt][2], acc[mt][nt][3]);
        }
}

// ---------------- vsum = sum_j v[b,j,:] ----------------
__global__ __launch_bounds__(256) void vsum_part_kernel() {
    int b = blockIdx.y, sp = blockIdx.x;
    int t = threadIdx.x;
    float s = 0.f;
    int j0 = sp * 256;
    for (int j = 0; j < 256; j++)
        s += g_kv[((size_t)(b*NTOK + j0 + j))*512 + 256 + t];
    g_vsp[(b*16+sp)*256 + t] = s;
}
__global__ __launch_bounds__(256) void vsum_reduce_kernel() {
    int b = blockIdx.x, t = threadIdx.x;
    float s = 0.f;
    for (int sp = 0; sp < 16; sp++) s += g_vsp[(b*16+sp)*256 + t];
    g_vsum[b*256 + t] = s;
}

// ---------------- slot LN + q projection ----------------
__global__ __launch_bounds__(256) void qproj_kernel(const float* __restrict__ lng,
                                                    const float* __restrict__ lnb) {
    __shared__ float s_ln[256];
    __shared__ float sh[16];
    int t = threadIdx.x;
    int bi = blockIdx.x;
    float xv = g_slots[(size_t)bi*256 + t];
    float2 r = blockReduce2(xv, xv*xv, sh);
    float m = r.x * (1.0f/256.0f);
    float var = r.y * (1.0f/256.0f) - m*m;
    float rs = rsqrtf(var + 1e-5f);
    s_ln[t] = (xv - m)*rs*lng[t] + lnb[t];
    __syncthreads();
    float acc = 0.f;
    for (int c = 0; c < 256; c++) acc += s_ln[c] * g_wqt[c*256 + t];
    g_q[(size_t)bi*256 + t] = acc;
}

// ---------------- attention pass ----------------
#define QS_CSTRIDE 80     // 4 groups * 20
#define KV_RSTRIDE 320    // 16 groups * 20
__global__ __launch_bounds__(256) void attn_kernel(float* __restrict__ attn_out, int lastIter) {
    __shared__ float qs[CHAN * QS_CSTRIDE];
    __shared__ float ks[8][KV_RSTRIDE];
    __shared__ float vs[8][KV_RSTRIDE];
    __shared__ float wsum[8][8];
    int b = blockIdx.y, sp = blockIdx.x;
    int tid = threadIdx.x;
    #pragma unroll
    for (int it = 0; it < 4; it++) {
        int idx = tid + it*256;
        int dlin = idx * 4;
        int c = dlin >> 6, rem = dlin & 63;
        int grp = rem >> 4, within = rem & 15;
        float4 v4 = *(const float4*)(g_q + (size_t)b*4096 + dlin);
        *(float4*)&qs[c*QS_CSTRIDE + grp*20 + within] = v4;
    }
    int c = tid >> 2, qd = tid & 3, h = c & 3;
    int grpIdx = h*4 + qd;
    float accA[16] = {};
    float accS = 0.f;
    int lane = tid & 31, wid = tid >> 5;
    int j0base = sp * 256;

    for (int ch = 0; ch < 32; ch++) {
        __syncthreads();
        int j0 = j0base + ch*8;
        #pragma unroll
        for (int it = 0; it < 4; it++) {
            int idx = tid + it*256;
            int r = idx >> 7, w = idx & 127;
            float4 v4 = *(const float4*)(g_kv + ((size_t)(b*NTOK + j0 + r))*512 + w*4);
            int g16 = (w >> 2) & 15;
            int off = g16*20 + (w & 3)*4;
            if (w < 64) *(float4*)&ks[r][off] = v4;
            else        *(float4*)&vs[r][off] = v4;
        }
        __syncthreads();
        float e[8];
        #pragma unroll
        for (int r = 0; r < 8; r++) {
            const float* qp = &qs[c*QS_CSTRIDE + qd*20];
            const float* kp = &ks[r][grpIdx*20];
            float pd = 0.f;
            #pragma unroll
            for (int dd = 0; dd < 16; dd += 4) {
                float4 qa = *(const float4*)(qp + dd);
                float4 ka = *(const float4*)(kp + dd);
                pd += qa.x*ka.x + qa.y*ka.y + qa.z*ka.z + qa.w*ka.w;
            }
            pd += __shfl_xor_sync(0xffffffffu, pd, 1);
            pd += __shfl_xor_sync(0xffffffffu, pd, 2);
            float ev = __expf(pd * SCALE);
            e[r] = ev;
            float val = (qd == 0) ? ev : 0.f;
            #pragma unroll
            for (int off = 16; off; off >>= 1) val += __shfl_xor_sync(0xffffffffu, val, off);
            if (lane == 0) wsum[wid][r] = val;
        }
        __syncthreads();
        #pragma unroll
        for (int r = 0; r < 8; r++) {
            float tot = 0.f;
            #pragma unroll
            for (int w = 0; w < 8; w++) tot += wsum[w][r];
            float attn = e[r] / tot;
            accS += attn;
            const float* vp = &vs[r][grpIdx*20];
            #pragma unroll
            for (int dd = 0; dd < 16; dd += 4) {
                float4 va = *(const float4*)(vp + dd);
                accA[dd+0] += attn * va.x;
                accA[dd+1] += attn * va.y;
                accA[dd+2] += attn * va.z;
                accA[dd+3] += attn * va.w;
            }
            if (lastIter) {
                float shv = attn + __shfl_xor_sync(0xffffffffu, attn, 4);
                shv += __shfl_xor_sync(0xffffffffu, shv, 8);
                if ((tid & 15) == 0) {
                    int slot = tid >> 4;
                    attn_out[((size_t)(b*KSLOT + slot))*NTOK + j0 + r] = shv * 0.25f;
                }
            }
        }
    }
    size_t base = ((size_t)((b*16 + sp)*CHAN + c))*DH + qd*16;
    #pragma unroll
    for (int dd = 0; dd < 16; dd += 4)
        *(float4*)(g_Apart + base + dd) = make_float4(accA[dd], accA[dd+1], accA[dd+2], accA[dd+3]);
    if (qd == 0) g_Spart[(b*16 + sp)*CHAN + c] = accS;
}

// ---------------- update: normalize + GRU + FF, 4 slots per block ----------------
__global__ __launch_bounds__(256) void update_kernel(
        const float* __restrict__ gbih, const float* __restrict__ gbhh,
        const float* __restrict__ ffg, const float* __restrict__ ffb,
        const float* __restrict__ fb1, const float* __restrict__ fb2,
        float* __restrict__ out_slots, int last) {
    __shared__ float u4 [4][256];
    __shared__ float h4 [4][256];
    __shared__ float hn4[4][256];
    __shared__ float ln4[4][256];
    __shared__ float h1s[4][1024];
    __shared__ float sh[16];
    int t = threadIdx.x;
    int base = blockIdx.x * 4;
    int b = base >> 4;
    int hh = t >> 6, d = t & 63;
    float vsm = g_vsum[b*256 + t];
    #pragma unroll
    for (int s = 0; s < 4; s++) {
        int i = (base + s) & 15;
        int c = i*NHEAD + hh;
        float A = 0.f, S0 = 0.f;
        #pragma unroll
        for (int sp = 0; sp < 16; sp++) {
            A  += g_Apart[((size_t)((b*16+sp)*CHAN + c))*DH + d];
            S0 += g_Spart[(b*16+sp)*CHAN + c];
        }
        float S = S0 + (float)NTOK * EPSW;
        u4[s][t] = (A + EPSW * vsm) / S;
        h4[s][t] = g_slots[(size_t)(base+s)*256 + t];
    }
    __syncthreads();
    float gir[4] = {}, giz[4] = {}, gin[4] = {};
    float ghr[4] = {}, ghz[4] = {}, ghn[4] = {};
    for (int cc = 0; cc < 256; cc++) {
        float wr = g_wih_t[cc*768 + t];
        float wz = g_wih_t[cc*768 + 256 + t];
        float wn = g_wih_t[cc*768 + 512 + t];
        float vr = g_whh_t[cc*768 + t];
        float vz = g_whh_t[cc*768 + 256 + t];
        float vn = g_whh_t[cc*768 + 512 + t];
        #pragma unroll
        for (int s = 0; s < 4; s++) {
            float xv = u4[s][cc], hv = h4[s][cc];
            gir[s] += wr*xv; giz[s] += wz*xv; gin[s] += wn*xv;
            ghr[s] += vr*hv; ghz[s] += vz*hv; ghn[s] += vn*hv;
        }
    }
    float bir = gbih[t], biz = gbih[256+t], bin = gbih[512+t];
    float bhr = gbhh[t], bhz = gbhh[256+t], bhn = gbhh[512+t];
    #pragma unroll
    for (int s = 0; s < 4; s++) {
        float r = sigmoidf_(gir[s] + bir + ghr[s] + bhr);
        float z = sigmoidf_(giz[s] + biz + ghz[s] + bhz);
        float n = tanhf(gin[s] + bin + r*(ghn[s] + bhn));
        hn4[s][t] = (1.0f - z)*n + z*h4[s][t];
    }
    __syncthreads();
    #pragma unroll
    for (int s = 0; s < 4; s++) {
        float v = hn4[s][t];
        float2 r = blockReduce2(v, v*v, sh);
        float m = r.x * (1.0f/256.0f);
        float var = r.y * (1.0f/256.0f) - m*m;
        float rs = rsqrtf(var + 1e-5f);
        ln4[s][t] = (v - m)*rs*ffg[t] + ffb[t];
    }
    __syncthreads();
    float a1[4][4] = {};
    for (int cc = 0; cc < 256; cc++) {
        float w0 = g_wf1t[cc*1024 + t];
        float w1 = g_wf1t[cc*1024 + 256 + t];
        float w2 = g_wf1t[cc*1024 + 512 + t];
        float w3 = g_wf1t[cc*1024 + 768 + t];
        #pragma unroll
        for (int s = 0; s < 4; s++) {
            float xv = ln4[s][cc];
            a1[s][0] += w0*xv; a1[s][1] += w1*xv; a1[s][2] += w2*xv; a1[s][3] += w3*xv;
        }
    }
    #pragma unroll
    for (int s = 0; s < 4; s++) {
        #pragma unroll
        for (int q = 0; q < 4; q++) {
            int row = q*256 + t;
            h1s[s][row] = gelu_exact(a1[s][q] + fb1[row]);
        }
    }
    __syncthreads();
    float o[4];
    #pragma unroll
    for (int s = 0; s < 4; s++) o[s] = hn4[s][t] + fb2[t];
    for (int j = 0; j < 1024; j++) {
        float w = g_wf2t[j*256 + t];
        #pragma unroll
        for (int s = 0; s < 4; s++) o[s] += w * h1s[s][j];
    }
    #pragma unroll
    for (int s = 0; s < 4; s++) {
        g_slots[(size_t)(base+s)*256 + t] = o[s];
        if (last) out_slots[(size_t)(base+s)*256 + t] = o[s];
    }
}

// ---------------- launch ----------------
extern "C" void kernel_launch(void* const* d_in, const int* in_sizes, int n_in,
                              void* d_out, int out_size) {
    const float* inputs   = (const float*)d_in[0];
    const float* cond     = (const float*)d_in[1];
    const float* to_q_w   = (const float*)d_in[2];
    const float* to_k_w   = (const float*)d_in[3];
    const float* to_v_w   = (const float*)d_in[4];
    const float* gru_w_ih = (const float*)d_in[5];
    const float* gru_w_hh = (const float*)d_in[6];
    const float* gru_b_ih = (const float*)d_in[7];
    const float* gru_b_hh = (const float*)d_in[8];
    const float* ln_in_g  = (const float*)d_in[9];
    const float* ln_in_b  = (const float*)d_in[10];
    const float* ln_sl_g  = (const float*)d_in[11];
    const float* ln_sl_b  = (const float*)d_in[12];
    const float* ff_ln_g  = (const float*)d_in[13];
    const float* ff_ln_b  = (const float*)d_in[14];
    const float* ff_w1    = (const float*)d_in[15];
    const float* ff_b1    = (const float*)d_in[16];
    const float* ff_w2    = (const float*)d_in[17];
    const float* ff_b2    = (const float*)d_in[18];
    float* out = (float*)d_out;
    float* out_attn = out + BATCH*KSLOT*256;   // slots first, then attn_out

    prep_kernel<<<1024, 256>>>(to_k_w, to_v_w, gru_w_ih, gru_w_hh, ff_w1, ff_w2, to_q_w, cond);
    ln_convert_kernel<<<MROWS, 256>>>(inputs, ln_in_g, ln_in_b);
    gemm_kv_mma<<<dim3(512/GBN, MROWS/GBM), 256>>>();
    vsum_part_kernel<<<dim3(16, BATCH), 256>>>();
    vsum_reduce_kernel<<<BATCH, 256>>>();

    for (int it = 0; it < ITERS; it++) {
        int last = (it == ITERS - 1) ? 1 : 0;
        qproj_kernel<<<BATCH*KSLOT, 256>>>(ln_sl_g, ln_sl_b);
        attn_kernel<<<dim3(16, BATCH), 256>>>(out_attn, last);
        update_kernel<<<BATCH*KSLOT/4, 256>>>(gru_b_ih, gru_b_hh, ff_ln_g, ff_ln_b,
                                              ff_b1, ff_b2, out, last);
    }
}

// round 7
// speedup vs baseline: 1.7198x; 1.0285x over previous
#include <cuda_runtime.h>
#include <cuda_bf16.h>
#include <cstdint>

// ---------------- problem constants ----------------
#define BATCH 32
#define NTOK  4096
#define FEAT  768
#define DIM   256
#define KVQ   256
#define NHEAD 4
#define DH    64
#define KSLOT 16
#define CHAN  64            // KSLOT * NHEAD
#define ITERS 3
#define EPSW  1e-8f
#define SCALE 0.125f        // DH^-0.5
#define MROWS (BATCH*NTOK)  // 131072

// GEMM config (mma.sync bf16, 3-term split via K-concat)
#define GBM 128
#define GBN 128
#define GBK 64
#define KEFF 2304           // 768 hi*hi + 768 hi*lo + 768 lo*hi
#define KSTAGES (KEFF/GBK)  // 36
#define GEMM_STAGE_BYTES 32768   // A 16KB + B 16KB
#define GEMM_DSMEM (2*GEMM_STAGE_BYTES + 1024)

// ---------------- scratch (device globals; no allocation allowed) ----------------
__device__ __align__(16) __nv_bfloat16 g_a2[(size_t)MROWS*1536]; // [m][0:768)=hi, [768:1536)=lo (LN'd input)
__device__ __align__(16) __nv_bfloat16 g_b2[512*KEFF];           // [n][k]: k<768 hi, <1536 lo, <2304 hi
__device__ float g_wqt [256*256];     // [c][o]
__device__ float g_wih_t[256*768];    // [c][row]
__device__ float g_whh_t[256*768];
__device__ float g_wf1t[256*1024];    // [c][row]
__device__ float g_wf2t[1024*256];    // [j][t]
__device__ float g_kv  [(size_t)MROWS*512];   // per token: k[0:256] | v[256:512]
__device__ float g_q   [BATCH*KSLOT*256];
__device__ float g_slots[BATCH*KSLOT*256];
__device__ float g_vsp [BATCH*16*256];
__device__ float g_vsum[BATCH*256];
__device__ float g_Apart[BATCH*16*CHAN*DH];   // [b][split][c][d]
__device__ float g_Spart[BATCH*16*CHAN];

// ---------------- PTX helpers (base-target only: cp.async / ldmatrix / mma.sync) ----
__device__ __forceinline__ uint32_t smem_u32(const void* p) {
    uint32_t a;
    asm("{ .reg .u64 t; cvta.to.shared.u64 t, %1; cvt.u32.u64 %0, t; }" : "=r"(a) : "l"(p));
    return a;
}
#define SWZ128(off) ((off) ^ (((off) >> 3) & 0x70))
#define CP16(dst, src) asm volatile("cp.async.cg.shared.global [%0], [%1], 16;" :: "r"(dst), "l"(src))
#define CP_COMMIT()    asm volatile("cp.async.commit_group;" ::: "memory")
#define CP_WAIT0()     asm volatile("cp.async.wait_group 0;" ::: "memory")

#define LDSM4(R, addr) \
  asm volatile("ldmatrix.sync.aligned.m8n8.x4.shared.b16 {%0,%1,%2,%3}, [%4];" \
    : "=r"((R)[0]), "=r"((R)[1]), "=r"((R)[2]), "=r"((R)[3]) : "r"(addr))

#define MMA16816(C, A, B0, B1) \
  asm volatile("mma.sync.aligned.m16n8k16.row.col.f32.bf16.bf16.f32 " \
    "{%0,%1,%2,%3}, {%4,%5,%6,%7}, {%8,%9}, {%0,%1,%2,%3};" \
    : "+f"((C)[0]), "+f"((C)[1]), "+f"((C)[2]), "+f"((C)[3]) \
    : "r"((A)[0]), "r"((A)[1]), "r"((A)[2]), "r"((A)[3]), "r"(B0), "r"(B1))

// ---------------- generic helpers ----------------
__device__ __forceinline__ float2 blockReduce2(float a, float b, float* sh) {
    __syncthreads();
    #pragma unroll
    for (int off = 16; off; off >>= 1) {
        a += __shfl_xor_sync(0xffffffffu, a, off);
        b += __shfl_xor_sync(0xffffffffu, b, off);
    }
    int wid = threadIdx.x >> 5, lane = threadIdx.x & 31;
    if (lane == 0) { sh[wid*2] = a; sh[wid*2+1] = b; }
    __syncthreads();
    float ra = 0.f, rb = 0.f;
    #pragma unroll
    for (int w = 0; w < 8; w++) { ra += sh[w*2]; rb += sh[w*2+1]; }
    return make_float2(ra, rb);
}
__device__ __forceinline__ float sigmoidf_(float x) { return 1.0f / (1.0f + __expf(-x)); }
__device__ __forceinline__ float gelu_exact(float x) { return 0.5f * x * (1.0f + erff(x * 0.70710678118654752f)); }

// ---------------- prep: weight transposes + split-bf16 B ----------------
__global__ void prep_kernel(const float* __restrict__ kw, const float* __restrict__ vw,
                            const float* __restrict__ wih, const float* __restrict__ whh,
                            const float* __restrict__ f1, const float* __restrict__ f2,
                            const float* __restrict__ qw) {
    int idx = blockIdx.x * blockDim.x + threadIdx.x;
    int stride = gridDim.x * blockDim.x;
    for (int p = idx; p < 512*KEFF; p += stride) {
        int n = p / KEFF, kk = p - n*KEFF;
        int k = (kk < 768) ? kk : ((kk < 1536) ? kk - 768 : kk - 1536);
        float src = (n < 256) ? kw[n*768 + k] : vw[(n-256)*768 + k];
        __nv_bfloat16 h = __float2bfloat16(src);
        if (kk >= 768 && kk < 1536) h = __float2bfloat16(src - __bfloat162float(h));
        g_b2[p] = h;
    }
    for (int p = idx; p < 256*768; p += stride) {
        int c = p / 768, r = p - c*768;
        g_wih_t[p] = wih[r*256 + c];
        g_whh_t[p] = whh[r*256 + c];
    }
    for (int p = idx; p < 256*1024; p += stride) g_wf1t[p] = f1[(p & 1023)*256 + (p >> 10)];
    for (int p = idx; p < 1024*256; p += stride) g_wf2t[p] = f2[(p & 255)*1024 + (p >> 8)];
    for (int p = idx; p < 256*256; p += stride)  g_wqt[p]  = qw[(p & 255)*256 + (p >> 8)];
}

// slots init split out so gemm_kv_mma sits at launch index 3 (ncu capture slot)
__global__ void slots_init_kernel(const float* __restrict__ cond) {
    int idx = blockIdx.x * blockDim.x + threadIdx.x;
    if (idx < BATCH*KSLOT*256) g_slots[idx] = cond[idx];
}

// ---------------- fused LN + split-bf16 conversion of inputs ----------------
__global__ __launch_bounds__(256) void ln_convert_kernel(const float* __restrict__ x,
                                                         const float* __restrict__ lng,
                                                         const float* __restrict__ lnb) {
    __shared__ float sh[16];
    size_t row = blockIdx.x;
    const float* xr = x + row * FEAT;
    int t = threadIdx.x;
    float v0 = xr[t], v1 = xr[t+256], v2 = xr[t+512];
    float2 r = blockReduce2(v0+v1+v2, v0*v0 + v1*v1 + v2*v2, sh);
    float m = r.x * (1.0f/768.0f);
    float var = r.y * (1.0f/768.0f) - m*m;
    float rs = rsqrtf(var + 1e-5f);
    __nv_bfloat16* dst = g_a2 + row * 1536;
    float vv[3] = {v0, v1, v2};
    #pragma unroll
    for (int i = 0; i < 3; i++) {
        int col = t + i*256;
        float val = (vv[i] - m)*rs*lng[col] + lnb[col];
        __nv_bfloat16 hi = __float2bfloat16(val);
        __nv_bfloat16 lo = __float2bfloat16(val - __bfloat162float(hi));
        dst[col] = hi;
        dst[768 + col] = lo;
    }
}

// ---------------- k|v projection GEMM via mma.sync bf16 ----------------
// C[131072, 512] = A2 x B2^T, single K=2304 bf16 GEMM (3-term split).
// Segment pairing: kk in [0,768): A hi * B hi; [768,1536): A hi * B lo; [1536,2304): A lo * B hi.
__device__ __forceinline__ void gemm_load_stage(int tid, int m0, int bn0, int ks, uint32_t sbase) {
    int kk = ks * GBK;
    int ka = (kk < 768) ? kk : kk - 768;
    uint32_t sA = sbase;
    uint32_t sB = sbase + 16384;
    #pragma unroll
    for (int i = 0; i < 4; i++) {
        int c = tid + i*256;
        int row = c >> 3, seg = c & 7;
        const char* src = (const char*)g_a2 + ((size_t)(m0+row)*1536 + ka)*2 + seg*16;
        CP16(sA + SWZ128((uint32_t)(row*128 + seg*16)), src);
    }
    #pragma unroll
    for (int i = 0; i < 4; i++) {
        int c = tid + i*256;
        int row = c >> 3, seg = c & 7;
        const char* src = (const char*)g_b2 + ((size_t)(bn0+row)*KEFF + kk)*2 + seg*16;
        CP16(sB + SWZ128((uint32_t)(row*128 + seg*16)), src);
    }
}

__global__ __launch_bounds__(256, 2) void gemm_kv_mma() {
    extern __shared__ char dynsm[];
    uint32_t sbase = (smem_u32(dynsm) + 1023u) & ~1023u;
    const int tid = threadIdx.x;
    const int wid = tid >> 5, lane = tid & 31;
    const int m0  = blockIdx.y * GBM;
    const int bn0 = blockIdx.x * GBN;
    const int wm = wid >> 1, wn = wid & 1;   // warp tile: 32x64 at (wm*32, wn*64)

    float acc[2][8][4];
    #pragma unroll
    for (int a = 0; a < 2; a++)
        #pragma unroll
        for (int b = 0; b < 8; b++)
            #pragma unroll
            for (int c = 0; c < 4; c++) acc[a][b][c] = 0.f;

    gemm_load_stage(tid, m0, bn0, 0, sbase);
    CP_COMMIT();

    // precomputed ldmatrix lane addressing
    const int a_row = wm*32 + (lane & 15);
    const int a_col = (lane >> 4) << 4;           // 0 or 16 bytes
    const int b_g = lane >> 3, b_r = lane & 7;
    const int b_row_in = ((b_g >> 1) << 3) + b_r; // row within 16-row group
    const int b_col = (b_g & 1) << 4;

    for (int ks = 0; ks < KSTAGES; ks++) {
        CP_WAIT0();
        __syncthreads();
        if (ks + 1 < KSTAGES) {
            gemm_load_stage(tid, m0, bn0, ks + 1, sbase + ((ks + 1) & 1) * GEMM_STAGE_BYTES);
            CP_COMMIT();
        }
        uint32_t sA = sbase + (ks & 1) * GEMM_STAGE_BYTES;
        uint32_t sB = sA + 16384;
        #pragma unroll
        for (int k16 = 0; k16 < 4; k16++) {
            uint32_t afr[2][4], bfr[4][4];
            #pragma unroll
            for (int mt = 0; mt < 2; mt++) {
                uint32_t addr = sA + SWZ128((uint32_t)((a_row + mt*16)*128 + k16*32 + a_col));
                LDSM4(afr[mt], addr);
            }
            #pragma unroll
            for (int p = 0; p < 4; p++) {
                uint32_t addr = sB + SWZ128((uint32_t)((wn*64 + p*16 + b_row_in)*128 + k16*32 + b_col));
                LDSM4(bfr[p], addr);
            }
            #pragma unroll
            for (int mt = 0; mt < 2; mt++)
                #pragma unroll
                for (int nt = 0; nt < 8; nt++) {
                    int p = nt >> 1, h = nt & 1;
                    MMA16816(acc[mt][nt], afr[mt], bfr[p][h*2], bfr[p][h*2+1]);
                }
        }
        __syncthreads();
    }

    // epilogue: fp32 accumulators -> g_kv
    int quad = lane >> 2, qid = lane & 3;
    #pragma unroll
    for (int mt = 0; mt < 2; mt++)
        #pragma unroll
        for (int nt = 0; nt < 8; nt++) {
            int mrow = m0 + wm*32 + mt*16 + quad;
            int col  = bn0 + wn*64 + nt*8 + qid*2;
            *(float2*)(g_kv + (size_t)mrow*512 + col)     = make_float2(acc[mt][nt][0], acc[mt][nt][1]);
            *(float2*)(g_kv + (size_t)(mrow+8)*512 + col) = make_float2(acc[mt][nt][2], acc[mt][nt][3]);
        }
}

// ---------------- vsum = sum_j v[b,j,:] ----------------
__global__ __launch_bounds__(256) void vsum_part_kernel() {
    int b = blockIdx.y, sp = blockIdx.x;
    int t = threadIdx.x;
    float s = 0.f;
    int j0 = sp * 256;
    for (int j = 0; j < 256; j++)
        s += g_kv[((size_t)(b*NTOK + j0 + j))*512 + 256 + t];
    g_vsp[(b*16+sp)*256 + t] = s;
}
__global__ __launch_bounds__(256) void vsum_reduce_kernel() {
    int b = blockIdx.x, t = threadIdx.x;
    float s = 0.f;
    for (int sp = 0; sp < 16; sp++) s += g_vsp[(b*16+sp)*256 + t];
    g_vsum[b*256 + t] = s;
}

// ---------------- slot LN + q projection ----------------
__global__ __launch_bounds__(256) void qproj_kernel(const float* __restrict__ lng,
                                                    const float* __restrict__ lnb) {
    __shared__ float s_ln[256];
    __shared__ float sh[16];
    int t = threadIdx.x;
    int bi = blockIdx.x;
    float xv = g_slots[(size_t)bi*256 + t];
    float2 r = blockReduce2(xv, xv*xv, sh);
    float m = r.x * (1.0f/256.0f);
    float var = r.y * (1.0f/256.0f) - m*m;
    float rs = rsqrtf(var + 1e-5f);
    s_ln[t] = (xv - m)*rs*lng[t] + lnb[t];
    __syncthreads();
    float acc = 0.f;
    for (int c = 0; c < 256; c++) acc += s_ln[c] * g_wqt[c*256 + t];
    g_q[(size_t)bi*256 + t] = acc;
}

// ---------------- attention pass ----------------
#define QS_CSTRIDE 80     // 4 groups * 20
#define KV_RSTRIDE 320    // 16 groups * 20
__global__ __launch_bounds__(256) void attn_kernel(float* __restrict__ attn_out, int lastIter) {
    __shared__ float qs[CHAN * QS_CSTRIDE];
    __shared__ float ks[8][KV_RSTRIDE];
    __shared__ float vs[8][KV_RSTRIDE];
    __shared__ float wsum[8][8];
    int b = blockIdx.y, sp = blockIdx.x;
    int tid = threadIdx.x;
    #pragma unroll
    for (int it = 0; it < 4; it++) {
        int idx = tid + it*256;
        int dlin = idx * 4;
        int c = dlin >> 6, rem = dlin & 63;
        int grp = rem >> 4, within = rem & 15;
        float4 v4 = *(const float4*)(g_q + (size_t)b*4096 + dlin);
        *(float4*)&qs[c*QS_CSTRIDE + grp*20 + within] = v4;
    }
    int c = tid >> 2, qd = tid & 3, h = c & 3;
    int grpIdx = h*4 + qd;
    float accA[16] = {};
    float accS = 0.f;
    int lane = tid & 31, wid = tid >> 5;
    int j0base = sp * 256;

    for (int ch = 0; ch < 32; ch++) {
        __syncthreads();
        int j0 = j0base + ch*8;
        #pragma unroll
        for (int it = 0; it < 4; it++) {
            int idx = tid + it*256;
            int r = idx >> 7, w = idx & 127;
            float4 v4 = *(const float4*)(g_kv + ((size_t)(b*NTOK + j0 + r))*512 + w*4);
            int g16 = (w >> 2) & 15;
            int off = g16*20 + (w & 3)*4;
            if (w < 64) *(float4*)&ks[r][off] = v4;
            else        *(float4*)&vs[r][off] = v4;
        }
        __syncthreads();
        float e[8];
        #pragma unroll
        for (int r = 0; r < 8; r++) {
            const float* qp = &qs[c*QS_CSTRIDE + qd*20];
            const float* kp = &ks[r][grpIdx*20];
            float pd = 0.f;
            #pragma unroll
            for (int dd = 0; dd < 16; dd += 4) {
                float4 qa = *(const float4*)(qp + dd);
                float4 ka = *(const float4*)(kp + dd);
                pd += qa.x*ka.x + qa.y*ka.y + qa.z*ka.z + qa.w*ka.w;
            }
            pd += __shfl_xor_sync(0xffffffffu, pd, 1);
            pd += __shfl_xor_sync(0xffffffffu, pd, 2);
            float ev = __expf(pd * SCALE);
            e[r] = ev;
            float val = (qd == 0) ? ev : 0.f;
            #pragma unroll
            for (int off = 16; off; off >>= 1) val += __shfl_xor_sync(0xffffffffu, val, off);
            if (lane == 0) wsum[wid][r] = val;
        }
        __syncthreads();
        #pragma unroll
        for (int r = 0; r < 8; r++) {
            float tot = 0.f;
            #pragma unroll
            for (int w = 0; w < 8; w++) tot += wsum[w][r];
            float attn = e[r] / tot;
            accS += attn;
            const float* vp = &vs[r][grpIdx*20];
            #pragma unroll
            for (int dd = 0; dd < 16; dd += 4) {
                float4 va = *(const float4*)(vp + dd);
                accA[dd+0] += attn * va.x;
                accA[dd+1] += attn * va.y;
                accA[dd+2] += attn * va.z;
                accA[dd+3] += attn * va.w;
            }
            if (lastIter) {
                float shv = attn + __shfl_xor_sync(0xffffffffu, attn, 4);
                shv += __shfl_xor_sync(0xffffffffu, shv, 8);
                if ((tid & 15) == 0) {
                    int slot = tid >> 4;
                    attn_out[((size_t)(b*KSLOT + slot))*NTOK + j0 + r] = shv * 0.25f;
                }
            }
        }
    }
    size_t base = ((size_t)((b*16 + sp)*CHAN + c))*DH + qd*16;
    #pragma unroll
    for (int dd = 0; dd < 16; dd += 4)
        *(float4*)(g_Apart + base + dd) = make_float4(accA[dd], accA[dd+1], accA[dd+2], accA[dd+3]);
    if (qd == 0) g_Spart[(b*16 + sp)*CHAN + c] = accS;
}

// ---------------- update: normalize + GRU + FF, 4 slots per block ----------------
__global__ __launch_bounds__(256) void update_kernel(
        const float* __restrict__ gbih, const float* __restrict__ gbhh,
        const float* __restrict__ ffg, const float* __restrict__ ffb,
        const float* __restrict__ fb1, const float* __restrict__ fb2,
        float* __restrict__ out_slots, int last) {
    __shared__ float u4 [4][256];
    __shared__ float h4 [4][256];
    __shared__ float hn4[4][256];
    __shared__ float ln4[4][256];
    __shared__ float h1s[4][1024];
    __shared__ float sh[16];
    int t = threadIdx.x;
    int base = blockIdx.x * 4;
    int b = base >> 4;
    int hh = t >> 6, d = t & 63;
    float vsm = g_vsum[b*256 + t];
    #pragma unroll
    for (int s = 0; s < 4; s++) {
        int i = (base + s) & 15;
        int c = i*NHEAD + hh;
        float A = 0.f, S0 = 0.f;
        #pragma unroll
        for (int sp = 0; sp < 16; sp++) {
            A  += g_Apart[((size_t)((b*16+sp)*CHAN + c))*DH + d];
            S0 += g_Spart[(b*16+sp)*CHAN + c];
        }
        float S = S0 + (float)NTOK * EPSW;
        u4[s][t] = (A + EPSW * vsm) / S;
        h4[s][t] = g_slots[(size_t)(base+s)*256 + t];
    }
    __syncthreads();
    float gir[4] = {}, giz[4] = {}, gin[4] = {};
    float ghr[4] = {}, ghz[4] = {}, ghn[4] = {};
    for (int cc = 0; cc < 256; cc++) {
        float wr = g_wih_t[cc*768 + t];
        float wz = g_wih_t[cc*768 + 256 + t];
        float wn = g_wih_t[cc*768 + 512 + t];
        float vr = g_whh_t[cc*768 + t];
        float vz = g_whh_t[cc*768 + 256 + t];
        float vn = g_whh_t[cc*768 + 512 + t];
        #pragma unroll
        for (int s = 0; s < 4; s++) {
            float xv = u4[s][cc], hv = h4[s][cc];
            gir[s] += wr*xv; giz[s] += wz*xv; gin[s] += wn*xv;
            ghr[s] += vr*hv; ghz[s] += vz*hv; ghn[s] += vn*hv;
        }
    }
    float bir = gbih[t], biz = gbih[256+t], bin = gbih[512+t];
    float bhr = gbhh[t], bhz = gbhh[256+t], bhn = gbhh[512+t];
    #pragma unroll
    for (int s = 0; s < 4; s++) {
        float r = sigmoidf_(gir[s] + bir + ghr[s] + bhr);
        float z = sigmoidf_(giz[s] + biz + ghz[s] + bhz);
        float n = tanhf(gin[s] + bin + r*(ghn[s] + bhn));
        hn4[s][t] = (1.0f - z)*n + z*h4[s][t];
    }
    __syncthreads();
    #pragma unroll
    for (int s = 0; s < 4; s++) {
        float v = hn4[s][t];
        float2 r = blockReduce2(v, v*v, sh);
        float m = r.x * (1.0f/256.0f);
        float var = r.y * (1.0f/256.0f) - m*m;
        float rs = rsqrtf(var + 1e-5f);
        ln4[s][t] = (v - m)*rs*ffg[t] + ffb[t];
    }
    __syncthreads();
    float a1[4][4] = {};
    for (int cc = 0; cc < 256; cc++) {
        float w0 = g_wf1t[cc*1024 + t];
        float w1 = g_wf1t[cc*1024 + 256 + t];
        float w2 = g_wf1t[cc*1024 + 512 + t];
        float w3 = g_wf1t[cc*1024 + 768 + t];
        #pragma unroll
        for (int s = 0; s < 4; s++) {
            float xv = ln4[s][cc];
            a1[s][0] += w0*xv; a1[s][1] += w1*xv; a1[s][2] += w2*xv; a1[s][3] += w3*xv;
        }
    }
    #pragma unroll
    for (int s = 0; s < 4; s++) {
        #pragma unroll
        for (int q = 0; q < 4; q++) {
            int row = q*256 + t;
            h1s[s][row] = gelu_exact(a1[s][q] + fb1[row]);
        }
    }
    __syncthreads();
    float o[4];
    #pragma unroll
    for (int s = 0; s < 4; s++) o[s] = hn4[s][t] + fb2[t];
    for (int j = 0; j < 1024; j++) {
        float w = g_wf2t[j*256 + t];
        #pragma unroll
        for (int s = 0; s < 4; s++) o[s] += w * h1s[s][j];
    }
    #pragma unroll
    for (int s = 0; s < 4; s++) {
        g_slots[(size_t)(base+s)*256 + t] = o[s];
        if (last) out_slots[(size_t)(base+s)*256 + t] = o[s];
    }
}

// ---------------- launch ----------------
extern "C" void kernel_launch(void* const* d_in, const int* in_sizes, int n_in,
                              void* d_out, int out_size) {
    const float* inputs   = (const float*)d_in[0];
    const float* cond     = (const float*)d_in[1];
    const float* to_q_w   = (const float*)d_in[2];
    const float* to_k_w   = (const float*)d_in[3];
    const float* to_v_w   = (const float*)d_in[4];
    const float* gru_w_ih = (const float*)d_in[5];
    const float* gru_w_hh = (const float*)d_in[6];
    const float* gru_b_ih = (const float*)d_in[7];
    const float* gru_b_hh = (const float*)d_in[8];
    const float* ln_in_g  = (const float*)d_in[9];
    const float* ln_in_b  = (const float*)d_in[10];
    const float* ln_sl_g  = (const float*)d_in[11];
    const float* ln_sl_b  = (const float*)d_in[12];
    const float* ff_ln_g  = (const float*)d_in[13];
    const float* ff_ln_b  = (const float*)d_in[14];
    const float* ff_w1    = (const float*)d_in[15];
    const float* ff_b1    = (const float*)d_in[16];
    const float* ff_w2    = (const float*)d_in[17];
    const float* ff_b2    = (const float*)d_in[18];
    float* out = (float*)d_out;
    float* out_attn = out + BATCH*KSLOT*256;   // slots first, then attn_out

    // idempotent, called every time (no static guards); not an allocation
    cudaFuncSetAttribute(gemm_kv_mma, cudaFuncAttributeMaxDynamicSharedMemorySize, GEMM_DSMEM);

    prep_kernel<<<1024, 256>>>(to_k_w, to_v_w, gru_w_ih, gru_w_hh, ff_w1, ff_w2, to_q_w);  // 0
    ln_convert_kernel<<<MROWS, 256>>>(inputs, ln_in_g, ln_in_b);                           // 1
    slots_init_kernel<<<BATCH*KSLOT, 256>>>(cond);                                         // 2
    gemm_kv_mma<<<dim3(512/GBN, MROWS/GBM), 256, GEMM_DSMEM>>>();                          // 3 (ncu slot)
    vsum_part_kernel<<<dim3(16, BATCH), 256>>>();
    vsum_reduce_kernel<<<BATCH, 256>>>();

    for (int it = 0; it < ITERS; it++) {
        int last = (it == ITERS - 1) ? 1 : 0;
        qproj_kernel<<<BATCH*KSLOT, 256>>>(ln_sl_g, ln_sl_b);
        attn_kernel<<<dim3(16, BATCH), 256>>>(out_attn, last);
        update_kernel<<<BATCH*KSLOT/4, 256>>>(gru_b_ih, gru_b_hh, ff_ln_g, ff_ln_b,
                                              ff_b1, ff_b2, out, last);
    }
}

// round 8
// speedup vs baseline: 1.7748x; 1.0320x over previous
#include <cuda_runtime.h>
#include <cuda_bf16.h>
#include <cstdint>

// ---------------- problem constants ----------------
#define BATCH 32
#define NTOK  4096
#define FEAT  768
#define DIM   256
#define KVQ   256
#define NHEAD 4
#define DH    64
#define KSLOT 16
#define CHAN  64            // KSLOT * NHEAD
#define ITERS 3
#define EPSW  1e-8f
#define SCALE 0.125f        // DH^-0.5
#define MROWS (BATCH*NTOK)  // 131072
#define SPLITS 32           // attention N-splits (tokens per block = 128)

// GEMM config (mma.sync bf16, 3-term split via K-concat)
#define GBM 128
#define GBN 128
#define GBK 64
#define KEFF 2304           // 768 hi*hi + 768 hi*lo + 768 lo*hi
#define KSTAGES (KEFF/GBK)  // 36
#define GEMM_STAGE_BYTES 32768   // A 16KB + B 16KB
#define GEMM_DSMEM (2*GEMM_STAGE_BYTES + 1024)

// ---------------- scratch (device globals; no allocation allowed) ----------------
__device__ __align__(16) __nv_bfloat16 g_a2[(size_t)MROWS*1536]; // [m][0:768)=hi, [768:1536)=lo
__device__ __align__(16) __nv_bfloat16 g_b2[512*KEFF];           // [n][k]: hi|lo|hi
__device__ float g_wqt [256*256];     // [c][o]
__device__ float g_wih_t[256*768];    // [c][row]
__device__ float g_whh_t[256*768];
__device__ float g_wf1t[256*1024];    // [c][row]
__device__ float g_wf2t[1024*256];    // [j][t]
__device__ float g_kv  [(size_t)MROWS*512];   // per token: k[0:256] | v[256:512]
__device__ float g_q   [BATCH*KSLOT*256];
__device__ float g_slots[BATCH*KSLOT*256];
__device__ float g_vsp [BATCH*16*256];
__device__ float g_vsum[BATCH*256];
__device__ float g_Apart[BATCH*SPLITS*CHAN*DH];   // [b][split][c][d]
__device__ float g_Spart[BATCH*SPLITS*CHAN];

// ---------------- PTX helpers ----------------
__device__ __forceinline__ uint32_t smem_u32(const void* p) {
    uint32_t a;
    asm("{ .reg .u64 t; cvta.to.shared.u64 t, %1; cvt.u32.u64 %0, t; }" : "=r"(a) : "l"(p));
    return a;
}
#define SWZ128(off) ((off) ^ (((off) >> 3) & 0x70))
#define CP16(dst, src) asm volatile("cp.async.cg.shared.global [%0], [%1], 16;" :: "r"(dst), "l"(src))
#define CP_COMMIT()    asm volatile("cp.async.commit_group;" ::: "memory")
#define CP_WAIT0()     asm volatile("cp.async.wait_group 0;" ::: "memory")

#define LDSM4(R, addr) \
  asm volatile("ldmatrix.sync.aligned.m8n8.x4.shared.b16 {%0,%1,%2,%3}, [%4];" \
    : "=r"((R)[0]), "=r"((R)[1]), "=r"((R)[2]), "=r"((R)[3]) : "r"(addr))

#define MMA16816(C, A, B0, B1) \
  asm volatile("mma.sync.aligned.m16n8k16.row.col.f32.bf16.bf16.f32 " \
    "{%0,%1,%2,%3}, {%4,%5,%6,%7}, {%8,%9}, {%0,%1,%2,%3};" \
    : "+f"((C)[0]), "+f"((C)[1]), "+f"((C)[2]), "+f"((C)[3]) \
    : "r"((A)[0]), "r"((A)[1]), "r"((A)[2]), "r"((A)[3]), "r"(B0), "r"(B1))

// ---------------- generic helpers ----------------
__device__ __forceinline__ float2 blockReduce2(float a, float b, float* sh) {
    __syncthreads();
    #pragma unroll
    for (int off = 16; off; off >>= 1) {
        a += __shfl_xor_sync(0xffffffffu, a, off);
        b += __shfl_xor_sync(0xffffffffu, b, off);
    }
    int wid = threadIdx.x >> 5, lane = threadIdx.x & 31;
    if (lane == 0) { sh[wid*2] = a; sh[wid*2+1] = b; }
    __syncthreads();
    float ra = 0.f, rb = 0.f;
    #pragma unroll
    for (int w = 0; w < 8; w++) { ra += sh[w*2]; rb += sh[w*2+1]; }
    return make_float2(ra, rb);
}
__device__ __forceinline__ float sigmoidf_(float x) { return 1.0f / (1.0f + __expf(-x)); }
__device__ __forceinline__ float gelu_exact(float x) { return 0.5f * x * (1.0f + erff(x * 0.70710678118654752f)); }
__device__ __forceinline__ float rcp_fast(float x) { float r; asm("rcp.approx.f32 %0, %1;" : "=f"(r) : "f"(x)); return r; }

// ---------------- prep: weight transposes + split-bf16 B + slots init ----------------
__global__ void prep_kernel(const float* __restrict__ kw, const float* __restrict__ vw,
                            const float* __restrict__ wih, const float* __restrict__ whh,
                            const float* __restrict__ f1, const float* __restrict__ f2,
                            const float* __restrict__ qw, const float* __restrict__ cond) {
    int idx = blockIdx.x * blockDim.x + threadIdx.x;
    int stride = gridDim.x * blockDim.x;
    for (int p = idx; p < 512*KEFF; p += stride) {
        int n = p / KEFF, kk = p - n*KEFF;
        int k = (kk < 768) ? kk : ((kk < 1536) ? kk - 768 : kk - 1536);
        float src = (n < 256) ? kw[n*768 + k] : vw[(n-256)*768 + k];
        __nv_bfloat16 h = __float2bfloat16(src);
        if (kk >= 768 && kk < 1536) h = __float2bfloat16(src - __bfloat162float(h));
        g_b2[p] = h;
    }
    for (int p = idx; p < 256*768; p += stride) {
        int c = p / 768, r = p - c*768;
        g_wih_t[p] = wih[r*256 + c];
        g_whh_t[p] = whh[r*256 + c];
    }
    for (int p = idx; p < 256*1024; p += stride) g_wf1t[p] = f1[(p & 1023)*256 + (p >> 10)];
    for (int p = idx; p < 1024*256; p += stride) g_wf2t[p] = f2[(p & 255)*1024 + (p >> 8)];
    for (int p = idx; p < 256*256; p += stride)  g_wqt[p]  = qw[(p & 255)*256 + (p >> 8)];
    for (int p = idx; p < BATCH*KSLOT*256; p += stride) g_slots[p] = cond[p];
}

// ---------------- fused: input LN+split-convert  AND  iter-0 qproj (independent) ----
__global__ __launch_bounds__(256) void lnq_kernel(const float* __restrict__ x,
                                                  const float* __restrict__ lng,
                                                  const float* __restrict__ lnb,
                                                  const float* __restrict__ cond,
                                                  const float* __restrict__ slng,
                                                  const float* __restrict__ slnb) {
    __shared__ float sh[16];
    __shared__ float s_ln[256];
    int t = threadIdx.x;
    if (blockIdx.x < MROWS) {
        size_t row = blockIdx.x;
        const float* xr = x + row * FEAT;
        float v0 = xr[t], v1 = xr[t+256], v2 = xr[t+512];
        float2 r = blockReduce2(v0+v1+v2, v0*v0 + v1*v1 + v2*v2, sh);
        float m = r.x * (1.0f/768.0f);
        float var = r.y * (1.0f/768.0f) - m*m;
        float rs = rsqrtf(var + 1e-5f);
        __nv_bfloat16* dst = g_a2 + row * 1536;
        float vv[3] = {v0, v1, v2};
        #pragma unroll
        for (int i = 0; i < 3; i++) {
            int col = t + i*256;
            float val = (vv[i] - m)*rs*lng[col] + lnb[col];
            __nv_bfloat16 hi = __float2bfloat16(val);
            __nv_bfloat16 lo = __float2bfloat16(val - __bfloat162float(hi));
            dst[col] = hi;
            dst[768 + col] = lo;
        }
    } else {
        int bi = blockIdx.x - MROWS;           // 0..511
        float xv = cond[(size_t)bi*256 + t];
        float2 r = blockReduce2(xv, xv*xv, sh);
        float m = r.x * (1.0f/256.0f);
        float var = r.y * (1.0f/256.0f) - m*m;
        float rs = rsqrtf(var + 1e-5f);
        s_ln[t] = (xv - m)*rs*slng[t] + slnb[t];
        __syncthreads();
        float acc = 0.f;
        for (int c = 0; c < 256; c++) acc += s_ln[c] * g_wqt[c*256 + t];
        g_q[(size_t)bi*256 + t] = acc;
    }
}

// ---------------- k|v projection GEMM via mma.sync bf16 ----------------
__device__ __forceinline__ void gemm_load_stage(int tid, int m0, int bn0, int ks, uint32_t sbase) {
    int kk = ks * GBK;
    int ka = (kk < 768) ? kk : kk - 768;
    uint32_t sA = sbase;
    uint32_t sB = sbase + 16384;
    #pragma unroll
    for (int i = 0; i < 4; i++) {
        int c = tid + i*256;
        int row = c >> 3, seg = c & 7;
        const char* src = (const char*)g_a2 + ((size_t)(m0+row)*1536 + ka)*2 + seg*16;
        CP16(sA + SWZ128((uint32_t)(row*128 + seg*16)), src);
    }
    #pragma unroll
    for (int i = 0; i < 4; i++) {
        int c = tid + i*256;
        int row = c >> 3, seg = c & 7;
        const char* src = (const char*)g_b2 + ((size_t)(bn0+row)*KEFF + kk)*2 + seg*16;
        CP16(sB + SWZ128((uint32_t)(row*128 + seg*16)), src);
    }
}

__global__ __launch_bounds__(256, 2) void gemm_kv_mma() {
    extern __shared__ char dynsm[];
    uint32_t sbase = (smem_u32(dynsm) + 1023u) & ~1023u;
    const int tid = threadIdx.x;
    const int wid = tid >> 5, lane = tid & 31;
    const int m0  = blockIdx.y * GBM;
    const int bn0 = blockIdx.x * GBN;
    const int wm = wid >> 1, wn = wid & 1;   // warp tile: 32x64

    float acc[2][8][4];
    #pragma unroll
    for (int a = 0; a < 2; a++)
        #pragma unroll
        for (int b = 0; b < 8; b++)
            #pragma unroll
            for (int c = 0; c < 4; c++) acc[a][b][c] = 0.f;

    gemm_load_stage(tid, m0, bn0, 0, sbase);
    CP_COMMIT();

    const int a_row = wm*32 + (lane & 15);
    const int a_col = (lane >> 4) << 4;
    const int b_g = lane >> 3, b_r = lane & 7;
    const int b_row_in = ((b_g >> 1) << 3) + b_r;
    const int b_col = (b_g & 1) << 4;

    for (int ks = 0; ks < KSTAGES; ks++) {
        CP_WAIT0();
        __syncthreads();
        if (ks + 1 < KSTAGES) {
            gemm_load_stage(tid, m0, bn0, ks + 1, sbase + ((ks + 1) & 1) * GEMM_STAGE_BYTES);
            CP_COMMIT();
        }
        uint32_t sA = sbase + (ks & 1) * GEMM_STAGE_BYTES;
        uint32_t sB = sA + 16384;
        #pragma unroll
        for (int k16 = 0; k16 < 4; k16++) {
            uint32_t afr[2][4], bfr[4][4];
            #pragma unroll
            for (int mt = 0; mt < 2; mt++) {
                uint32_t addr = sA + SWZ128((uint32_t)((a_row + mt*16)*128 + k16*32 + a_col));
                LDSM4(afr[mt], addr);
            }
            #pragma unroll
            for (int p = 0; p < 4; p++) {
                uint32_t addr = sB + SWZ128((uint32_t)((wn*64 + p*16 + b_row_in)*128 + k16*32 + b_col));
                LDSM4(bfr[p], addr);
            }
            #pragma unroll
            for (int mt = 0; mt < 2; mt++)
                #pragma unroll
                for (int nt = 0; nt < 8; nt++) {
                    int p = nt >> 1, h = nt & 1;
                    MMA16816(acc[mt][nt], afr[mt], bfr[p][h*2], bfr[p][h*2+1]);
                }
        }
        __syncthreads();
    }

    int quad = lane >> 2, qid = lane & 3;
    #pragma unroll
    for (int mt = 0; mt < 2; mt++)
        #pragma unroll
        for (int nt = 0; nt < 8; nt++) {
            int mrow = m0 + wm*32 + mt*16 + quad;
            int col  = bn0 + wn*64 + nt*8 + qid*2;
            *(float2*)(g_kv + (size_t)mrow*512 + col)     = make_float2(acc[mt][nt][0], acc[mt][nt][1]);
            *(float2*)(g_kv + (size_t)(mrow+8)*512 + col) = make_float2(acc[mt][nt][2], acc[mt][nt][3]);
        }
}

// ---------------- vsum = sum_j v[b,j,:] ----------------
__global__ __launch_bounds__(256) void vsum_part_kernel() {
    int b = blockIdx.y, sp = blockIdx.x;
    int t = threadIdx.x;
    float s = 0.f;
    int j0 = sp * 256;
    for (int j = 0; j < 256; j++)
        s += g_kv[((size_t)(b*NTOK + j0 + j))*512 + 256 + t];
    g_vsp[(b*16+sp)*256 + t] = s;
}
__global__ __launch_bounds__(256) void vsum_reduce_kernel() {
    int b = blockIdx.x, t = threadIdx.x;
    float s = 0.f;
    for (int sp = 0; sp < 16; sp++) s += g_vsp[(b*16+sp)*256 + t];
    g_vsum[b*256 + t] = s;
}

// ---------------- slot LN + q projection (iters >= 1) ----------------
__global__ __launch_bounds__(256) void qproj_kernel(const float* __restrict__ lng,
                                                    const float* __restrict__ lnb) {
    __shared__ float s_ln[256];
    __shared__ float sh[16];
    int t = threadIdx.x;
    int bi = blockIdx.x;
    float xv = g_slots[(size_t)bi*256 + t];
    float2 r = blockReduce2(xv, xv*xv, sh);
    float m = r.x * (1.0f/256.0f);
    float var = r.y * (1.0f/256.0f) - m*m;
    float rs = rsqrtf(var + 1e-5f);
    s_ln[t] = (xv - m)*rs*lng[t] + lnb[t];
    __syncthreads();
    float acc = 0.f;
    for (int c = 0; c < 256; c++) acc += s_ln[c] * g_wqt[c*256 + t];
    g_q[(size_t)bi*256 + t] = acc;
}

// ---------------- attention pass ----------------
#define KV_RSTRIDE 320    // 16 groups * 20 (padded, conflict-free LDS.128)
__global__ __launch_bounds__(256) void attn_kernel(float* __restrict__ attn_out, int lastIter) {
    __shared__ float ks[8][KV_RSTRIDE];
    __shared__ float vs[8][KV_RSTRIDE];
    __shared__ __align__(16) float wsum[8][8];
    int b = blockIdx.y, sp = blockIdx.x;
    int tid = threadIdx.x;
    int c = tid >> 2, qd = tid & 3, h = c & 3;
    int grpIdx = h*4 + qd;
    int lane = tid & 31, wid = tid >> 5;

    // q for this (c, qd): 16 floats, loop-invariant -> registers (coalesced LDG)
    float4 qreg[4];
    {
        const float* qp = g_q + (size_t)b*4096 + c*64 + qd*16;
        #pragma unroll
        for (int i = 0; i < 4; i++) qreg[i] = *(const float4*)(qp + i*4);
    }

    float accA[16] = {};
    float accS = 0.f;
    int j0base = sp * (NTOK/SPLITS);

    for (int ch = 0; ch < (NTOK/SPLITS)/8; ch++) {
        __syncthreads();
        int j0 = j0base + ch*8;
        #pragma unroll
        for (int it = 0; it < 4; it++) {
            int idx = tid + it*256;
            int r = idx >> 7, w = idx & 127;
            float4 v4 = *(const float4*)(g_kv + ((size_t)(b*NTOK + j0 + r))*512 + w*4);
            int g16 = (w >> 2) & 15;
            int off = g16*20 + (w & 3)*4;
            if (w < 64) *(float4*)&ks[r][off] = v4;
            else        *(float4*)&vs[r][off] = v4;
        }
        __syncthreads();
        float e[8];
        #pragma unroll
        for (int r = 0; r < 8; r++) {
            const float* kp = &ks[r][grpIdx*20];
            float pd = 0.f;
            #pragma unroll
            for (int dd = 0; dd < 4; dd++) {
                float4 ka = *(const float4*)(kp + dd*4);
                pd += qreg[dd].x*ka.x + qreg[dd].y*ka.y + qreg[dd].z*ka.z + qreg[dd].w*ka.w;
            }
            pd += __shfl_xor_sync(0xffffffffu, pd, 1);
            pd += __shfl_xor_sync(0xffffffffu, pd, 2);
            float ev = __expf(pd * SCALE);
            e[r] = ev;
            // channel-sum within warp: 3 shfl (qd lanes hold identical ev)
            float cs = ev;
            cs += __shfl_xor_sync(0xffffffffu, cs, 4);
            cs += __shfl_xor_sync(0xffffffffu, cs, 8);
            cs += __shfl_xor_sync(0xffffffffu, cs, 16);
            if (lane == 0) wsum[wid][r] = cs;
        }
        __syncthreads();
        // tot[r] = sum over 8 warps, via vectorized smem reads
        float4 t0 = make_float4(0.f,0.f,0.f,0.f), t1 = t0;
        #pragma unroll
        for (int w = 0; w < 8; w++) {
            float4 a = *(const float4*)&wsum[w][0];
            float4 bb = *(const float4*)&wsum[w][4];
            t0.x += a.x;  t0.y += a.y;  t0.z += a.z;  t0.w += a.w;
            t1.x += bb.x; t1.y += bb.y; t1.z += bb.z; t1.w += bb.w;
        }
        float tot[8] = {t0.x, t0.y, t0.z, t0.w, t1.x, t1.y, t1.z, t1.w};
        #pragma unroll
        for (int r = 0; r < 8; r++) {
            float attn = e[r] * rcp_fast(tot[r]);
            accS += attn;
            const float* vp = &vs[r][grpIdx*20];
            #pragma unroll
            for (int dd = 0; dd < 16; dd += 4) {
                float4 va = *(const float4*)(vp + dd);
                accA[dd+0] += attn * va.x;
                accA[dd+1] += attn * va.y;
                accA[dd+2] += attn * va.z;
                accA[dd+3] += attn * va.w;
            }
            if (lastIter) {
                float shv = attn + __shfl_xor_sync(0xffffffffu, attn, 4);
                shv += __shfl_xor_sync(0xffffffffu, shv, 8);
                if ((tid & 15) == 0) {
                    int slot = tid >> 4;
                    attn_out[((size_t)(b*KSLOT + slot))*NTOK + j0 + r] = shv * 0.25f;
                }
            }
        }
    }
    size_t base = ((size_t)((b*SPLITS + sp)*CHAN + c))*DH + qd*16;
    #pragma unroll
    for (int dd = 0; dd < 16; dd += 4)
        *(float4*)(g_Apart + base + dd) = make_float4(accA[dd], accA[dd+1], accA[dd+2], accA[dd+3]);
    if (qd == 0) g_Spart[(b*SPLITS + sp)*CHAN + c] = accS;
}

// ---------------- update: normalize + GRU + FF, 4 slots per block ----------------
__global__ __launch_bounds__(256) void update_kernel(
        const float* __restrict__ gbih, const float* __restrict__ gbhh,
        const float* __restrict__ ffg, const float* __restrict__ ffb,
        const float* __restrict__ fb1, const float* __restrict__ fb2,
        float* __restrict__ out_slots, int last) {
    __shared__ float u4 [4][256];
    __shared__ float h4 [4][256];
    __shared__ float hn4[4][256];
    __shared__ float ln4[4][256];
    __shared__ float h1s[4][1024];
    __shared__ float sh[16];
    int t = threadIdx.x;
    int base = blockIdx.x * 4;
    int b = base >> 4;
    int hh = t >> 6, d = t & 63;
    float vsm = g_vsum[b*256 + t];
    #pragma unroll
    for (int s = 0; s < 4; s++) {
        int i = (base + s) & 15;
        int c = i*NHEAD + hh;
        float A = 0.f, S0 = 0.f;
        #pragma unroll
        for (int sp = 0; sp < SPLITS; sp++) {
            A  += g_Apart[((size_t)((b*SPLITS+sp)*CHAN + c))*DH + d];
            S0 += g_Spart[(b*SPLITS+sp)*CHAN + c];
        }
        float S = S0 + (float)NTOK * EPSW;
        u4[s][t] = (A + EPSW * vsm) / S;
        h4[s][t] = g_slots[(size_t)(base+s)*256 + t];
    }
    __syncthreads();
    float gir[4] = {}, giz[4] = {}, gin[4] = {};
    float ghr[4] = {}, ghz[4] = {}, ghn[4] = {};
    for (int cc = 0; cc < 256; cc++) {
        float wr = g_wih_t[cc*768 + t];
        float wz = g_wih_t[cc*768 + 256 + t];
        float wn = g_wih_t[cc*768 + 512 + t];
        float vr = g_whh_t[cc*768 + t];
        float vz = g_whh_t[cc*768 + 256 + t];
        float vn = g_whh_t[cc*768 + 512 + t];
        #pragma unroll
        for (int s = 0; s < 4; s++) {
            float xv = u4[s][cc], hv = h4[s][cc];
            gir[s] += wr*xv; giz[s] += wz*xv; gin[s] += wn*xv;
            ghr[s] += vr*hv; ghz[s] += vz*hv; ghn[s] += vn*hv;
        }
    }
    float bir = gbih[t], biz = gbih[256+t], bin = gbih[512+t];
    float bhr = gbhh[t], bhz = gbhh[256+t], bhn = gbhh[512+t];
    #pragma unroll
    for (int s = 0; s < 4; s++) {
        float r = sigmoidf_(gir[s] + bir + ghr[s] + bhr);
        float z = sigmoidf_(giz[s] + biz + ghz[s] + bhz);
        float n = tanhf(gin[s] + bin + r*(ghn[s] + bhn));
        hn4[s][t] = (1.0f - z)*n + z*h4[s][t];
    }
    __syncthreads();
    #pragma unroll
    for (int s = 0; s < 4; s++) {
        float v = hn4[s][t];
        float2 r = blockReduce2(v, v*v, sh);
        float m = r.x * (1.0f/256.0f);
        float var = r.y * (1.0f/256.0f) - m*m;
        float rs = rsqrtf(var + 1e-5f);
        ln4[s][t] = (v - m)*rs*ffg[t] + ffb[t];
    }
    __syncthreads();
    float a1[4][4] = {};
    for (int cc = 0; cc < 256; cc++) {
        float w0 = g_wf1t[cc*1024 + t];
        float w1 = g_wf1t[cc*1024 + 256 + t];
        float w2 = g_wf1t[cc*1024 + 512 + t];
        float w3 = g_wf1t[cc*1024 + 768 + t];
        #pragma unroll
        for (int s = 0; s < 4; s++) {
            float xv = ln4[s][cc];
            a1[s][0] += w0*xv; a1[s][1] += w1*xv; a1[s][2] += w2*xv; a1[s][3] += w3*xv;
        }
    }
    #pragma unroll
    for (int s = 0; s < 4; s++) {
        #pragma unroll
        for (int q = 0; q < 4; q++) {
            int row = q*256 + t;
            h1s[s][row] = gelu_exact(a1[s][q] + fb1[row]);
        }
    }
    __syncthreads();
    float o[4];
    #pragma unroll
    for (int s = 0; s < 4; s++) o[s] = hn4[s][t] + fb2[t];
    for (int j = 0; j < 1024; j++) {
        float w = g_wf2t[j*256 + t];
        #pragma unroll
        for (int s = 0; s < 4; s++) o[s] += w * h1s[s][j];
    }
    #pragma unroll
    for (int s = 0; s < 4; s++) {
        g_slots[(size_t)(base+s)*256 + t] = o[s];
        if (last) out_slots[(size_t)(base+s)*256 + t] = o[s];
    }
}

// ---------------- launch ----------------
extern "C" void kernel_launch(void* const* d_in, const int* in_sizes, int n_in,
                              void* d_out, int out_size) {
    const float* inputs   = (const float*)d_in[0];
    const float* cond     = (const float*)d_in[1];
    const float* to_q_w   = (const float*)d_in[2];
    const float* to_k_w   = (const float*)d_in[3];
    const float* to_v_w   = (const float*)d_in[4];
    const float* gru_w_ih = (const float*)d_in[5];
    const float* gru_w_hh = (const float*)d_in[6];
    const float* gru_b_ih = (const float*)d_in[7];
    const float* gru_b_hh = (const float*)d_in[8];
    const float* ln_in_g  = (const float*)d_in[9];
    const float* ln_in_b  = (const float*)d_in[10];
    const float* ln_sl_g  = (const float*)d_in[11];
    const float* ln_sl_b  = (const float*)d_in[12];
    const float* ff_ln_g  = (const float*)d_in[13];
    const float* ff_ln_b  = (const float*)d_in[14];
    const float* ff_w1    = (const float*)d_in[15];
    const float* ff_b1    = (const float*)d_in[16];
    const float* ff_w2    = (const float*)d_in[17];
    const float* ff_b2    = (const float*)d_in[18];
    float* out = (float*)d_out;
    float* out_attn = out + BATCH*KSLOT*256;   // slots first, then attn_out

    cudaFuncSetAttribute(gemm_kv_mma, cudaFuncAttributeMaxDynamicSharedMemorySize, GEMM_DSMEM);

    prep_kernel<<<1024, 256>>>(to_k_w, to_v_w, gru_w_ih, gru_w_hh, ff_w1, ff_w2, to_q_w, cond); // 0
    lnq_kernel<<<MROWS + BATCH*KSLOT, 256>>>(inputs, ln_in_g, ln_in_b, cond, ln_sl_g, ln_sl_b); // 1
    gemm_kv_mma<<<dim3(512/GBN, MROWS/GBM), 256, GEMM_DSMEM>>>();                               // 2
    attn_kernel<<<dim3(SPLITS, BATCH), 256>>>(out_attn, 0);                                     // 3 (ncu slot)
    vsum_part_kernel<<<dim3(16, BATCH), 256>>>();                                               // 4
    vsum_reduce_kernel<<<BATCH, 256>>>();                                                       // 5
    update_kernel<<<BATCH*KSLOT/4, 256>>>(gru_b_ih, gru_b_hh, ff_ln_g, ff_ln_b,
                                          ff_b1, ff_b2, out, 0);                                // 6

    for (int it = 1; it < ITERS; it++) {
        int last = (it == ITERS - 1) ? 1 : 0;
        qproj_kernel<<<BATCH*KSLOT, 256>>>(ln_sl_g, ln_sl_b);
        attn_kernel<<<dim3(SPLITS, BATCH), 256>>>(out_attn, last);
        update_kernel<<<BATCH*KSLOT/4, 256>>>(gru_b_ih, gru_b_hh, ff_ln_g, ff_ln_b,
                                              ff_b1, ff_b2, out, last);
    }
}

// round 10
// speedup vs baseline: 1.8917x; 1.0659x over previous
#include <cuda_runtime.h>
#include <cuda_bf16.h>
#include <cstdint>

// ---------------- problem constants ----------------
#define BATCH 32
#define NTOK  4096
#define FEAT  768
#define DIM   256
#define KVQ   256
#define NHEAD 4
#define DH    64
#define KSLOT 16
#define CHAN  64            // KSLOT * NHEAD
#define ITERS 3
#define EPSW  1e-8f
#define SCALE 0.125f        // DH^-0.5
#define MROWS (BATCH*NTOK)  // 131072
#define SPLITS 32           // attention N-splits (tokens per block = 128)
#define TOKCH 16            // tokens per attention chunk

// GEMM config (mma.sync bf16, 3-term split via K-concat)
#define GBM 128
#define GBN 128
#define GBK 64
#define KEFF 2304
#define KSTAGES (KEFF/GBK)  // 36
#define GEMM_STAGE_BYTES 32768
#define GEMM_DSMEM (2*GEMM_STAGE_BYTES + 1024)

// attn dynamic smem: ks 16*384 + vs 16*384 + wsum 8*17 + tots 16
#define ATTN_SM_FLOATS (2*TOKCH*384 + 8*17 + 16)
#define ATTN_DSMEM (ATTN_SM_FLOATS*4)

// ---------------- scratch (device globals; no allocation allowed) ----------------
__device__ __align__(16) __nv_bfloat16 g_a2[(size_t)MROWS*1536]; // [m][hi|lo]
__device__ __align__(16) __nv_bfloat16 g_b2[512*KEFF];           // [n][hi|lo|hi]
__device__ float g_wqt [256*256];
__device__ float g_wih_t[256*768];
__device__ float g_whh_t[256*768];
__device__ float g_wf1t[256*1024];
__device__ float g_wf2t[1024*256];
__device__ float g_kv  [(size_t)MROWS*512];   // per token: k[0:256] | v[256:512]
__device__ float g_q   [BATCH*KSLOT*256];
__device__ float g_slots[BATCH*KSLOT*256];
__device__ float g_vsp [BATCH*16*256];
__device__ float g_vsum[BATCH*256];
__device__ float g_Apart[BATCH*SPLITS*CHAN*DH];
__device__ float g_Spart[BATCH*SPLITS*CHAN];

// ---------------- PTX helpers ----------------
__device__ __forceinline__ uint32_t smem_u32(const void* p) {
    uint32_t a;
    asm("{ .reg .u64 t; cvta.to.shared.u64 t, %1; cvt.u32.u64 %0, t; }" : "=r"(a) : "l"(p));
    return a;
}
#define SWZ128(off) ((off) ^ (((off) >> 3) & 0x70))
#define CP16(dst, src) asm volatile("cp.async.cg.shared.global [%0], [%1], 16;" :: "r"(dst), "l"(src))
#define CP_COMMIT()    asm volatile("cp.async.commit_group;" ::: "memory")
#define CP_WAIT0()     asm volatile("cp.async.wait_group 0;" ::: "memory")

#define LDSM4(R, addr) \
  asm volatile("ldmatrix.sync.aligned.m8n8.x4.shared.b16 {%0,%1,%2,%3}, [%4];" \
    : "=r"((R)[0]), "=r"((R)[1]), "=r"((R)[2]), "=r"((R)[3]) : "r"(addr))

#define MMA16816(C, A, B0, B1) \
  asm volatile("mma.sync.aligned.m16n8k16.row.col.f32.bf16.bf16.f32 " \
    "{%0,%1,%2,%3}, {%4,%5,%6,%7}, {%8,%9}, {%0,%1,%2,%3};" \
    : "+f"((C)[0]), "+f"((C)[1]), "+f"((C)[2]), "+f"((C)[3]) \
    : "r"((A)[0]), "r"((A)[1]), "r"((A)[2]), "r"((A)[3]), "r"(B0), "r"(B1))

// ---------------- generic helpers ----------------
__device__ __forceinline__ float2 blockReduce2(float a, float b, float* sh) {
    __syncthreads();
    #pragma unroll
    for (int off = 16; off; off >>= 1) {
        a += __shfl_xor_sync(0xffffffffu, a, off);
        b += __shfl_xor_sync(0xffffffffu, b, off);
    }
    int wid = threadIdx.x >> 5, lane = threadIdx.x & 31;
    if (lane == 0) { sh[wid*2] = a; sh[wid*2+1] = b; }
    __syncthreads();
    float ra = 0.f, rb = 0.f;
    #pragma unroll
    for (int w = 0; w < 8; w++) { ra += sh[w*2]; rb += sh[w*2+1]; }
    return make_float2(ra, rb);
}
__device__ __forceinline__ float sigmoidf_(float x) { return 1.0f / (1.0f + __expf(-x)); }
__device__ __forceinline__ float gelu_exact(float x) { return 0.5f * x * (1.0f + erff(x * 0.70710678118654752f)); }
__device__ __forceinline__ float rcp_fast(float x) { float r; asm("rcp.approx.f32 %0, %1;" : "=f"(r) : "f"(x)); return r; }

// ---------------- prep ----------------
__global__ void prep_kernel(const float* __restrict__ kw, const float* __restrict__ vw,
                            const float* __restrict__ wih, const float* __restrict__ whh,
                            const float* __restrict__ f1, const float* __restrict__ f2,
                            const float* __restrict__ qw, const float* __restrict__ cond) {
    int idx = blockIdx.x * blockDim.x + threadIdx.x;
    int stride = gridDim.x * blockDim.x;
    for (int p = idx; p < 512*KEFF; p += stride) {
        int n = p / KEFF, kk = p - n*KEFF;
        int k = (kk < 768) ? kk : ((kk < 1536) ? kk - 768 : kk - 1536);
        float src = (n < 256) ? kw[n*768 + k] : vw[(n-256)*768 + k];
        __nv_bfloat16 h = __float2bfloat16(src);
        if (kk >= 768 && kk < 1536) h = __float2bfloat16(src - __bfloat162float(h));
        g_b2[p] = h;
    }
    for (int p = idx; p < 256*768; p += stride) {
        int c = p / 768, r = p - c*768;
        g_wih_t[p] = wih[r*256 + c];
        g_whh_t[p] = whh[r*256 + c];
    }
    for (int p = idx; p < 256*1024; p += stride) g_wf1t[p] = f1[(p & 1023)*256 + (p >> 10)];
    for (int p = idx; p < 1024*256; p += stride) g_wf2t[p] = f2[(p & 255)*1024 + (p >> 8)];
    for (int p = idx; p < 256*256; p += stride)  g_wqt[p]  = qw[(p & 255)*256 + (p >> 8)];
    for (int p = idx; p < BATCH*KSLOT*256; p += stride) g_slots[p] = cond[p];
}

// ---------------- fused input LN+convert AND iter-0 qproj ----------------
__global__ __launch_bounds__(256) void lnq_kernel(const float* __restrict__ x,
                                                  const float* __restrict__ lng,
                                                  const float* __restrict__ lnb,
                                                  const float* __restrict__ cond,
                                                  const float* __restrict__ slng,
                                                  const float* __restrict__ slnb) {
    __shared__ float sh[16];
    __shared__ float s_ln[256];
    int t = threadIdx.x;
    if (blockIdx.x < MROWS) {
        size_t row = blockIdx.x;
        const float* xr = x + row * FEAT;
        float v0 = xr[t], v1 = xr[t+256], v2 = xr[t+512];
        float2 r = blockReduce2(v0+v1+v2, v0*v0 + v1*v1 + v2*v2, sh);
        float m = r.x * (1.0f/768.0f);
        float var = r.y * (1.0f/768.0f) - m*m;
        float rs = rsqrtf(var + 1e-5f);
        __nv_bfloat16* dst = g_a2 + row * 1536;
        float vv[3] = {v0, v1, v2};
        #pragma unroll
        for (int i = 0; i < 3; i++) {
            int col = t + i*256;
            float val = (vv[i] - m)*rs*lng[col] + lnb[col];
            __nv_bfloat16 hi = __float2bfloat16(val);
            __nv_bfloat16 lo = __float2bfloat16(val - __bfloat162float(hi));
            dst[col] = hi;
            dst[768 + col] = lo;
        }
    } else {
        int bi = blockIdx.x - MROWS;
        float xv = cond[(size_t)bi*256 + t];
        float2 r = blockReduce2(xv, xv*xv, sh);
        float m = r.x * (1.0f/256.0f);
        float var = r.y * (1.0f/256.0f) - m*m;
        float rs = rsqrtf(var + 1e-5f);
        s_ln[t] = (xv - m)*rs*slng[t] + slnb[t];
        __syncthreads();
        float acc = 0.f;
        for (int c = 0; c < 256; c++) acc += s_ln[c] * g_wqt[c*256 + t];
        g_q[(size_t)bi*256 + t] = acc;
    }
}

// ---------------- k|v projection GEMM via mma.sync bf16 ----------------
__device__ __forceinline__ void gemm_load_stage(int tid, int m0, int bn0, int ks, uint32_t sbase) {
    int kk = ks * GBK;
    int ka = (kk < 768) ? kk : kk - 768;
    uint32_t sA = sbase;
    uint32_t sB = sbase + 16384;
    #pragma unroll
    for (int i = 0; i < 4; i++) {
        int c = tid + i*256;
        int row = c >> 3, seg = c & 7;
        const char* src = (const char*)g_a2 + ((size_t)(m0+row)*1536 + ka)*2 + seg*16;
        CP16(sA + SWZ128((uint32_t)(row*128 + seg*16)), src);
    }
    #pragma unroll
    for (int i = 0; i < 4; i++) {
        int c = tid + i*256;
        int row = c >> 3, seg = c & 7;
        const char* src = (const char*)g_b2 + ((size_t)(bn0+row)*KEFF + kk)*2 + seg*16;
        CP16(sB + SWZ128((uint32_t)(row*128 + seg*16)), src);
    }
}

__global__ __launch_bounds__(256, 2) void gemm_kv_mma() {
    extern __shared__ char dynsm[];
    uint32_t sbase = (smem_u32(dynsm) + 1023u) & ~1023u;
    const int tid = threadIdx.x;
    const int wid = tid >> 5, lane = tid & 31;
    const int m0  = blockIdx.y * GBM;
    const int bn0 = blockIdx.x * GBN;
    const int wm = wid >> 1, wn = wid & 1;

    float acc[2][8][4];
    #pragma unroll
    for (int a = 0; a < 2; a++)
        #pragma unroll
        for (int b = 0; b < 8; b++)
            #pragma unroll
            for (int c = 0; c < 4; c++) acc[a][b][c] = 0.f;

    gemm_load_stage(tid, m0, bn0, 0, sbase);
    CP_COMMIT();

    const int a_row = wm*32 + (lane & 15);
    const int a_col = (lane >> 4) << 4;
    const int b_g = lane >> 3, b_r = lane & 7;
    const int b_row_in = ((b_g >> 1) << 3) + b_r;
    const int b_col = (b_g & 1) << 4;

    for (int ks = 0; ks < KSTAGES; ks++) {
        CP_WAIT0();
        __syncthreads();
        if (ks + 1 < KSTAGES) {
            gemm_load_stage(tid, m0, bn0, ks + 1, sbase + ((ks + 1) & 1) * GEMM_STAGE_BYTES);
            CP_COMMIT();
        }
        uint32_t sA = sbase + (ks & 1) * GEMM_STAGE_BYTES;
        uint32_t sB = sA + 16384;
        #pragma unroll
        for (int k16 = 0; k16 < 4; k16++) {
            uint32_t afr[2][4], bfr[4][4];
            #pragma unroll
            for (int mt = 0; mt < 2; mt++) {
                uint32_t addr = sA + SWZ128((uint32_t)((a_row + mt*16)*128 + k16*32 + a_col));
                LDSM4(afr[mt], addr);
            }
            #pragma unroll
            for (int p = 0; p < 4; p++) {
                uint32_t addr = sB + SWZ128((uint32_t)((wn*64 + p*16 + b_row_in)*128 + k16*32 + b_col));
                LDSM4(bfr[p], addr);
            }
            #pragma unroll
            for (int mt = 0; mt < 2; mt++)
                #pragma unroll
                for (int nt = 0; nt < 8; nt++) {
                    int p = nt >> 1, h = nt & 1;
                    MMA16816(acc[mt][nt], afr[mt], bfr[p][h*2], bfr[p][h*2+1]);
                }
        }
        __syncthreads();
    }

    int quad = lane >> 2, qid = lane & 3;
    #pragma unroll
    for (int mt = 0; mt < 2; mt++)
        #pragma unroll
        for (int nt = 0; nt < 8; nt++) {
            int mrow = m0 + wm*32 + mt*16 + quad;
            int col  = bn0 + wn*64 + nt*8 + qid*2;
            *(float2*)(g_kv + (size_t)mrow*512 + col)     = make_float2(acc[mt][nt][0], acc[mt][nt][1]);
            *(float2*)(g_kv + (size_t)(mrow+8)*512 + col) = make_float2(acc[mt][nt][2], acc[mt][nt][3]);
        }
}

// ---------------- vsum ----------------
__global__ __launch_bounds__(256) void vsum_part_kernel() {
    int b = blockIdx.y, sp = blockIdx.x;
    int t = threadIdx.x;
    float s = 0.f;
    int j0 = sp * 256;
    for (int j = 0; j < 256; j++)
        s += g_kv[((size_t)(b*NTOK + j0 + j))*512 + 256 + t];
    g_vsp[(b*16+sp)*256 + t] = s;
}
__global__ __launch_bounds__(256) void vsum_reduce_kernel() {
    int b = blockIdx.x, t = threadIdx.x;
    float s = 0.f;
    for (int sp = 0; sp < 16; sp++) s += g_vsp[(b*16+sp)*256 + t];
    g_vsum[b*256 + t] = s;
}

// ---------------- slot LN + q projection (iters >= 1) ----------------
__global__ __launch_bounds__(256) void qproj_kernel(const float* __restrict__ lng,
                                                    const float* __restrict__ lnb) {
    __shared__ float s_ln[256];
    __shared__ float sh[16];
    int t = threadIdx.x;
    int bi = blockIdx.x;
    float xv = g_slots[(size_t)bi*256 + t];
    float2 r = blockReduce2(xv, xv*xv, sh);
    float m = r.x * (1.0f/256.0f);
    float var = r.y * (1.0f/256.0f) - m*m;
    float rs = rsqrtf(var + 1e-5f);
    s_ln[t] = (xv - m)*rs*lng[t] + lnb[t];
    __syncthreads();
    float acc = 0.f;
    for (int c = 0; c < 256; c++) acc += s_ln[c] * g_wqt[c*256 + t];
    g_q[(size_t)bi*256 + t] = acc;
}

// ---------------- attention pass (2 channels/thread, 8-float d-slices) ----------
// smem: 8-float groups padded to 12 floats; lanes qd8*12 hit all 32 banks.
__global__ __launch_bounds__(256) void attn_kernel(float* __restrict__ attn_out, int lastIter) {
    extern __shared__ float dsm[];
    float* ksp  = dsm;                       // [TOKCH][384]
    float* vsp  = dsm + TOKCH*384;           // [TOKCH][384]
    float* wsum = dsm + 2*TOKCH*384;         // [8][17]
    float* tots = wsum + 8*17;               // [TOKCH] (stores reciprocals)

    int b = blockIdx.y, sp = blockIdx.x;
    int tid = threadIdx.x;
    int lane = tid & 31, wid = tid >> 5;
    int cg  = tid >> 3;          // channel pair base: channels cg and cg+32 (same head)
    int qd8 = tid & 7;           // 8-float d-slice
    int h   = cg & 3;
    int koff = (h*8 + qd8) * 12; // smem float offset of this thread's 8-float slice

    // q for both channels: 8 floats each -> 4 float4 regs
    float4 ql0, ql1, qh0, qh1;
    {
        const float* qp = g_q + (size_t)b*4096 + cg*64 + qd8*8;
        ql0 = *(const float4*)qp;       ql1 = *(const float4*)(qp + 4);
        qh0 = *(const float4*)(qp+2048); qh1 = *(const float4*)(qp + 2052);
    }

    float accA_lo[8] = {}, accA_hi[8] = {};
    float accS_lo = 0.f, accS_hi = 0.f;
    int j0base = sp * (NTOK/SPLITS);

    for (int ch = 0; ch < (NTOK/SPLITS)/TOKCH; ch++) {
        __syncthreads();
        int j0 = j0base + ch*TOKCH;
        // load 16 tokens x 512 floats = 2048 float4, 8 per thread
        #pragma unroll
        for (int it = 0; it < 8; it++) {
            int idx = tid + it*256;
            int r = idx >> 7, w4 = idx & 127;
            float4 v4 = *(const float4*)(g_kv + ((size_t)(b*NTOK + j0 + r))*512 + w4*4);
            int wl = w4 & 63;
            uint32_t off = r*384 + (wl >> 1)*12 + (wl & 1)*4;
            if (w4 < 64) *(float4*)&ksp[off] = v4;
            else         *(float4*)&vsp[off] = v4;
        }
        __syncthreads();

        float e_lo[TOKCH], e_hi[TOKCH];
        #pragma unroll
        for (int r = 0; r < TOKCH; r++) {
            const float* kp = &ksp[r*384 + koff];
            float4 k0 = *(const float4*)kp;
            float4 k1 = *(const float4*)(kp + 4);
            float pl = ql0.x*k0.x + ql0.y*k0.y + ql0.z*k0.z + ql0.w*k0.w
                     + ql1.x*k1.x + ql1.y*k1.y + ql1.z*k1.z + ql1.w*k1.w;
            float ph = qh0.x*k0.x + qh0.y*k0.y + qh0.z*k0.z + qh0.w*k0.w
                     + qh1.x*k1.x + qh1.y*k1.y + qh1.z*k1.z + qh1.w*k1.w;
            pl += __shfl_xor_sync(0xffffffffu, pl, 1);
            ph += __shfl_xor_sync(0xffffffffu, ph, 1);
            pl += __shfl_xor_sync(0xffffffffu, pl, 2);
            ph += __shfl_xor_sync(0xffffffffu, ph, 2);
            pl += __shfl_xor_sync(0xffffffffu, pl, 4);
            ph += __shfl_xor_sync(0xffffffffu, ph, 4);
            float el = __expf(pl * SCALE);
            float eh = __expf(ph * SCALE);
            e_lo[r] = el; e_hi[r] = eh;
            float cs = el + eh;
            cs += __shfl_xor_sync(0xffffffffu, cs, 8);
            cs += __shfl_xor_sync(0xffffffffu, cs, 16);
            if (lane == 0) wsum[wid*17 + r] = cs;
        }
        __syncthreads();
        // stage-2: tot[r] over 8 warps -> reciprocal broadcast
        if (tid < 128) {
            int rr = tid >> 3, ww = tid & 7;
            float vsm = wsum[ww*17 + rr];
            vsm += __shfl_xor_sync(0xffffffffu, vsm, 1);
            vsm += __shfl_xor_sync(0xffffffffu, vsm, 2);
            vsm += __shfl_xor_sync(0xffffffffu, vsm, 4);
            if (ww == 0) tots[rr] = rcp_fast(vsm);
        }
        __syncthreads();

        #pragma unroll
        for (int r = 0; r < TOKCH; r++) {
            float rt = tots[r];
            float alo = e_lo[r] * rt;
            float ahi = e_hi[r] * rt;
            accS_lo += alo; accS_hi += ahi;
            const float* vp = &vsp[r*384 + koff];
            float4 v0 = *(const float4*)vp;
            float4 v1 = *(const float4*)(vp + 4);
            accA_lo[0] += alo*v0.x; accA_lo[1] += alo*v0.y; accA_lo[2] += alo*v0.z; accA_lo[3] += alo*v0.w;
            accA_lo[4] += alo*v1.x; accA_lo[5] += alo*v1.y; accA_lo[6] += alo*v1.z; accA_lo[7] += alo*v1.w;
            accA_hi[0] += ahi*v0.x; accA_hi[1] += ahi*v0.y; accA_hi[2] += ahi*v0.z; accA_hi[3] += ahi*v0.w;
            accA_hi[4] += ahi*v1.x; accA_hi[5] += ahi*v1.y; accA_hi[6] += ahi*v1.z; accA_hi[7] += ahi*v1.w;
            if (lastIter) {
                // mean over heads: warp w owns slots w (lo) and w+8 (hi)
                float aol = alo + __shfl_xor_sync(0xffffffffu, alo, 8);
                float aoh = ahi + __shfl_xor_sync(0xffffffffu, ahi, 8);
                aol += __shfl_xor_sync(0xffffffffu, aol, 16);
                aoh += __shfl_xor_sync(0xffffffffu, aoh, 16);
                if (lane == 0) {
                    attn_out[((size_t)(b*KSLOT + wid))*NTOK + j0 + r]     = aol * 0.25f;
                    attn_out[((size_t)(b*KSLOT + wid + 8))*NTOK + j0 + r] = aoh * 0.25f;
                }
            }
        }
    }
    // write partials
    size_t base_lo = ((size_t)((b*SPLITS + sp)*CHAN + cg))*DH + qd8*8;
    size_t base_hi = ((size_t)((b*SPLITS + sp)*CHAN + cg + 32))*DH + qd8*8;
    *(float4*)(g_Apart + base_lo)     = make_float4(accA_lo[0], accA_lo[1], accA_lo[2], accA_lo[3]);
    *(float4*)(g_Apart + base_lo + 4) = make_float4(accA_lo[4], accA_lo[5], accA_lo[6], accA_lo[7]);
    *(float4*)(g_Apart + base_hi)     = make_float4(accA_hi[0], accA_hi[1], accA_hi[2], accA_hi[3]);
    *(float4*)(g_Apart + base_hi + 4) = make_float4(accA_hi[4], accA_hi[5], accA_hi[6], accA_hi[7]);
    if (qd8 == 0) {
        g_Spart[(b*SPLITS + sp)*CHAN + cg]      = accS_lo;
        g_Spart[(b*SPLITS + sp)*CHAN + cg + 32] = accS_hi;
    }
}

// ---------------- update: normalize + GRU + FF, 4 slots per block ----------------
__global__ __launch_bounds__(256) void update_kernel(
        const float* __restrict__ gbih, const float* __restrict__ gbhh,
        const float* __restrict__ ffg, const float* __restrict__ ffb,
        const float* __restrict__ fb1, const float* __restrict__ fb2,
        float* __restrict__ out_slots, int last) {
    __shared__ float u4 [4][256];
    __shared__ float h4 [4][256];
    __shared__ float hn4[4][256];
    __shared__ float ln4[4][256];
    __shared__ float h1s[4][1024];
    __shared__ float sh[16];
    int t = threadIdx.x;
    int base = blockIdx.x * 4;
    int b = base >> 4;
    int hh = t >> 6, d = t & 63;
    float vsm = g_vsum[b*256 + t];
    #pragma unroll
    for (int s = 0; s < 4; s++) {
        int i = (base + s) & 15;
        int c = i*NHEAD + hh;
        float A = 0.f, S0 = 0.f;
        #pragma unroll
        for (int sp = 0; sp < SPLITS; sp++) {
            A  += g_Apart[((size_t)((b*SPLITS+sp)*CHAN + c))*DH + d];
            S0 += g_Spart[(b*SPLITS+sp)*CHAN + c];
        }
        float S = S0 + (float)NTOK * EPSW;
        u4[s][t] = (A + EPSW * vsm) / S;
        h4[s][t] = g_slots[(size_t)(base+s)*256 + t];
    }
    __syncthreads();
    float gir[4] = {}, giz[4] = {}, gin[4] = {};
    float ghr[4] = {}, ghz[4] = {}, ghn[4] = {};
    for (int cc = 0; cc < 256; cc++) {
        float wr = g_wih_t[cc*768 + t];
        float wz = g_wih_t[cc*768 + 256 + t];
        float wn = g_wih_t[cc*768 + 512 + t];
        float vr = g_whh_t[cc*768 + t];
        float vz = g_whh_t[cc*768 + 256 + t];
        float vn = g_whh_t[cc*768 + 512 + t];
        #pragma unroll
        for (int s = 0; s < 4; s++) {
            float xv = u4[s][cc], hv = h4[s][cc];
            gir[s] += wr*xv; giz[s] += wz*xv; gin[s] += wn*xv;
            ghr[s] += vr*hv; ghz[s] += vz*hv; ghn[s] += vn*hv;
        }
    }
    float bir = gbih[t], biz = gbih[256+t], bin = gbih[512+t];
    float bhr = gbhh[t], bhz = gbhh[256+t], bhn = gbhh[512+t];
    #pragma unroll
    for (int s = 0; s < 4; s++) {
        float r = sigmoidf_(gir[s] + bir + ghr[s] + bhr);
        float z = sigmoidf_(giz[s] + biz + ghz[s] + bhz);
        float n = tanhf(gin[s] + bin + r*(ghn[s] + bhn));
        hn4[s][t] = (1.0f - z)*n + z*h4[s][t];
    }
    __syncthreads();
    #pragma unroll
    for (int s = 0; s < 4; s++) {
        float v = hn4[s][t];
        float2 r = blockReduce2(v, v*v, sh);
        float m = r.x * (1.0f/256.0f);
        float var = r.y * (1.0f/256.0f) - m*m;
        float rs = rsqrtf(var + 1e-5f);
        ln4[s][t] = (v - m)*rs*ffg[t] + ffb[t];
    }
    __syncthreads();
    float a1[4][4] = {};
    for (int cc = 0; cc < 256; cc++) {
        float w0 = g_wf1t[cc*1024 + t];
        float w1 = g_wf1t[cc*1024 + 256 + t];
        float w2 = g_wf1t[cc*1024 + 512 + t];
        float w3 = g_wf1t[cc*1024 + 768 + t];
        #pragma unroll
        for (int s = 0; s < 4; s++) {
            float xv = ln4[s][cc];
            a1[s][0] += w0*xv; a1[s][1] += w1*xv; a1[s][2] += w2*xv; a1[s][3] += w3*xv;
        }
    }
    #pragma unroll
    for (int s = 0; s < 4; s++) {
        #pragma unroll
        for (int q = 0; q < 4; q++) {
            int row = q*256 + t;
            h1s[s][row] = gelu_exact(a1[s][q] + fb1[row]);
        }
    }
    __syncthreads();
    float o[4];
    #pragma unroll
    for (int s = 0; s < 4; s++) o[s] = hn4[s][t] + fb2[t];
    for (int j = 0; j < 1024; j++) {
        float w = g_wf2t[j*256 + t];
        #pragma unroll
        for (int s = 0; s < 4; s++) o[s] += w * h1s[s][j];
    }
    #pragma unroll
    for (int s = 0; s < 4; s++) {
        g_slots[(size_t)(base+s)*256 + t] = o[s];
        if (last) out_slots[(size_t)(base+s)*256 + t] = o[s];
    }
}

// ---------------- launch ----------------
extern "C" void kernel_launch(void* const* d_in, const int* in_sizes, int n_in,
                              void* d_out, int out_size) {
    const float* inputs   = (const float*)d_in[0];
    const float* cond     = (const float*)d_in[1];
    const float* to_q_w   = (const float*)d_in[2];
    const float* to_k_w   = (const float*)d_in[3];
    const float* to_v_w   = (const float*)d_in[4];
    const float* gru_w_ih = (const float*)d_in[5];
    const float* gru_w_hh = (const float*)d_in[6];
    const float* gru_b_ih = (const float*)d_in[7];
    const float* gru_b_hh = (const float*)d_in[8];
    const float* ln_in_g  = (const float*)d_in[9];
    const float* ln_in_b  = (const float*)d_in[10];
    const float* ln_sl_g  = (const float*)d_in[11];
    const float* ln_sl_b  = (const float*)d_in[12];
    const float* ff_ln_g  = (const float*)d_in[13];
    const float* ff_ln_b  = (const float*)d_in[14];
    const float* ff_w1    = (const float*)d_in[15];
    const float* ff_b1    = (const float*)d_in[16];
    const float* ff_w2    = (const float*)d_in[17];
    const float* ff_b2    = (const float*)d_in[18];
    float* out = (float*)d_out;
    float* out_attn = out + BATCH*KSLOT*256;   // slots first, then attn_out

    cudaFuncSetAttribute(gemm_kv_mma, cudaFuncAttributeMaxDynamicSharedMemorySize, GEMM_DSMEM);
    cudaFuncSetAttribute(attn_kernel, cudaFuncAttributeMaxDynamicSharedMemorySize, ATTN_DSMEM);

    prep_kernel<<<1024, 256>>>(to_k_w, to_v_w, gru_w_ih, gru_w_hh, ff_w1, ff_w2, to_q_w, cond); // 0
    lnq_kernel<<<MROWS + BATCH*KSLOT, 256>>>(inputs, ln_in_g, ln_in_b, cond, ln_sl_g, ln_sl_b); // 1
    gemm_kv_mma<<<dim3(512/GBN, MROWS/GBM), 256, GEMM_DSMEM>>>();                               // 2
    attn_kernel<<<dim3(SPLITS, BATCH), 256, ATTN_DSMEM>>>(out_attn, 0);                         // 3 (ncu slot)
    vsum_part_kernel<<<dim3(16, BATCH), 256>>>();                                               // 4
    vsum_reduce_kernel<<<BATCH, 256>>>();                                                       // 5
    update_kernel<<<BATCH*KSLOT/4, 256>>>(gru_b_ih, gru_b_hh, ff_ln_g, ff_ln_b,
                                          ff_b1, ff_b2, out, 0);                                // 6

    for (int it = 1; it < ITERS; it++) {
        int last = (it == ITERS - 1) ? 1 : 0;
        qproj_kernel<<<BATCH*KSLOT, 256>>>(ln_sl_g, ln_sl_b);
        attn_kernel<<<dim3(SPLITS, BATCH), 256, ATTN_DSMEM>>>(out_attn, last);
        update_kernel<<<BATCH*KSLOT/4, 256>>>(gru_b_ih, gru_b_hh, ff_ln_g, ff_ln_b,
                                              ff_b1, ff_b2, out, last);
    }
}

// round 11
// speedup vs baseline: 1.9199x; 1.0149x over previous
#include <cuda_runtime.h>
#include <cuda_bf16.h>
#include <cstdint>

// ---------------- problem constants ----------------
#define BATCH 32
#define NTOK  4096
#define FEAT  768
#define DIM   256
#define KVQ   256
#define NHEAD 4
#define DH    64
#define KSLOT 16
#define CHAN  64            // KSLOT * NHEAD
#define ITERS 3
#define EPSW  1e-8f
#define SCALE 0.125f        // DH^-0.5
#define MROWS (BATCH*NTOK)  // 131072
#define SPLITS 32           // attention N-splits (tokens per block = 128)
#define TOKCH 16            // tokens per attention smem tile

// GEMM config (mma.sync bf16, 3-term split via K-concat)
#define GBM 128
#define GBN 128
#define GBK 64
#define KEFF 2304
#define KSTAGES (KEFF/GBK)  // 36
#define GEMM_STAGE_BYTES 32768
#define GEMM_DSMEM (3*GEMM_STAGE_BYTES + 1024)   // 3-stage ring

// attn dynamic smem: ks 16*384 + vs 16*384 + wsum 8*9 + tots 8
#define ATTN_SM_FLOATS (2*TOKCH*384 + 8*9 + 8)
#define ATTN_DSMEM (ATTN_SM_FLOATS*4)

// ---------------- scratch (device globals; no allocation allowed) ----------------
__device__ __align__(16) __nv_bfloat16 g_a2[(size_t)MROWS*1536]; // [m][hi|lo]
__device__ __align__(16) __nv_bfloat16 g_b2[512*KEFF];           // [n][hi|lo|hi]
__device__ float g_wqt [256*256];
__device__ float g_wih_t[256*768];
__device__ float g_whh_t[256*768];
__device__ float g_wf1t[256*1024];
__device__ float g_wf2t[1024*256];
__device__ float g_kv  [(size_t)MROWS*512];   // per token: k[0:256] | v[256:512]
__device__ float g_q   [BATCH*KSLOT*256];
__device__ float g_slots[BATCH*KSLOT*256];
__device__ float g_vsp [BATCH*16*256];
__device__ float g_vsum[BATCH*256];
__device__ float g_Apart[BATCH*SPLITS*CHAN*DH];
__device__ float g_Spart[BATCH*SPLITS*CHAN];

// ---------------- PTX helpers ----------------
__device__ __forceinline__ uint32_t smem_u32(const void* p) {
    uint32_t a;
    asm("{ .reg .u64 t; cvta.to.shared.u64 t, %1; cvt.u32.u64 %0, t; }" : "=r"(a) : "l"(p));
    return a;
}
#define SWZ128(off) ((off) ^ (((off) >> 3) & 0x70))
#define CP16(dst, src) asm volatile("cp.async.cg.shared.global [%0], [%1], 16;" :: "r"(dst), "l"(src))
#define CP_COMMIT()    asm volatile("cp.async.commit_group;" ::: "memory")
#define CP_WAITG(n)    asm volatile("cp.async.wait_group %0;" :: "n"(n) : "memory")

#define LDSM4(R, addr) \
  asm volatile("ldmatrix.sync.aligned.m8n8.x4.shared.b16 {%0,%1,%2,%3}, [%4];" \
    : "=r"((R)[0]), "=r"((R)[1]), "=r"((R)[2]), "=r"((R)[3]) : "r"(addr))

#define MMA16816(C, A, B0, B1) \
  asm volatile("mma.sync.aligned.m16n8k16.row.col.f32.bf16.bf16.f32 " \
    "{%0,%1,%2,%3}, {%4,%5,%6,%7}, {%8,%9}, {%0,%1,%2,%3};" \
    : "+f"((C)[0]), "+f"((C)[1]), "+f"((C)[2]), "+f"((C)[3]) \
    : "r"((A)[0]), "r"((A)[1]), "r"((A)[2]), "r"((A)[3]), "r"(B0), "r"(B1))

// ---------------- generic helpers ----------------
__device__ __forceinline__ float2 blockReduce2(float a, float b, float* sh) {
    __syncthreads();
    #pragma unroll
    for (int off = 16; off; off >>= 1) {
        a += __shfl_xor_sync(0xffffffffu, a, off);
        b += __shfl_xor_sync(0xffffffffu, b, off);
    }
    int wid = threadIdx.x >> 5, lane = threadIdx.x & 31;
    if (lane == 0) { sh[wid*2] = a; sh[wid*2+1] = b; }
    __syncthreads();
    float ra = 0.f, rb = 0.f;
    #pragma unroll
    for (int w = 0; w < 8; w++) { ra += sh[w*2]; rb += sh[w*2+1]; }
    return make_float2(ra, rb);
}
__device__ __forceinline__ float sigmoidf_(float x) { return 1.0f / (1.0f + __expf(-x)); }
__device__ __forceinline__ float gelu_exact(float x) { return 0.5f * x * (1.0f + erff(x * 0.70710678118654752f)); }
__device__ __forceinline__ float rcp_fast(float x) { float r; asm("rcp.approx.f32 %0, %1;" : "=f"(r) : "f"(x)); return r; }

// ---------------- prep ----------------
__global__ void prep_kernel(const float* __restrict__ kw, const float* __restrict__ vw,
                            const float* __restrict__ wih, const float* __restrict__ whh,
                            const float* __restrict__ f1, const float* __restrict__ f2,
                            const float* __restrict__ qw, const float* __restrict__ cond) {
    int idx = blockIdx.x * blockDim.x + threadIdx.x;
    int stride = gridDim.x * blockDim.x;
    for (int p = idx; p < 512*KEFF; p += stride) {
        int n = p / KEFF, kk = p - n*KEFF;
        int k = (kk < 768) ? kk : ((kk < 1536) ? kk - 768 : kk - 1536);
        float src = (n < 256) ? kw[n*768 + k] : vw[(n-256)*768 + k];
        __nv_bfloat16 h = __float2bfloat16(src);
        if (kk >= 768 && kk < 1536) h = __float2bfloat16(src - __bfloat162float(h));
        g_b2[p] = h;
    }
    for (int p = idx; p < 256*768; p += stride) {
        int c = p / 768, r = p - c*768;
        g_wih_t[p] = wih[r*256 + c];
        g_whh_t[p] = whh[r*256 + c];
    }
    for (int p = idx; p < 256*1024; p += stride) g_wf1t[p] = f1[(p & 1023)*256 + (p >> 10)];
    for (int p = idx; p < 1024*256; p += stride) g_wf2t[p] = f2[(p & 255)*1024 + (p >> 8)];
    for (int p = idx; p < 256*256; p += stride)  g_wqt[p]  = qw[(p & 255)*256 + (p >> 8)];
    for (int p = idx; p < BATCH*KSLOT*256; p += stride) g_slots[p] = cond[p];
}

// ---------------- fused input LN+convert AND iter-0 qproj ----------------
__global__ __launch_bounds__(256) void lnq_kernel(const float* __restrict__ x,
                                                  const float* __restrict__ lng,
                                                  const float* __restrict__ lnb,
                                                  const float* __restrict__ cond,
                                                  const float* __restrict__ slng,
                                                  const float* __restrict__ slnb) {
    __shared__ float sh[16];
    __shared__ float s_ln[256];
    int t = threadIdx.x;
    if (blockIdx.x < MROWS) {
        size_t row = blockIdx.x;
        const float* xr = x + row * FEAT;
        float v0 = xr[t], v1 = xr[t+256], v2 = xr[t+512];
        float2 r = blockReduce2(v0+v1+v2, v0*v0 + v1*v1 + v2*v2, sh);
        float m = r.x * (1.0f/768.0f);
        float var = r.y * (1.0f/768.0f) - m*m;
        float rs = rsqrtf(var + 1e-5f);
        __nv_bfloat16* dst = g_a2 + row * 1536;
        float vv[3] = {v0, v1, v2};
        #pragma unroll
        for (int i = 0; i < 3; i++) {
            int col = t + i*256;
            float val = (vv[i] - m)*rs*lng[col] + lnb[col];
            __nv_bfloat16 hi = __float2bfloat16(val);
            __nv_bfloat16 lo = __float2bfloat16(val - __bfloat162float(hi));
            dst[col] = hi;
            dst[768 + col] = lo;
        }
    } else {
        int bi = blockIdx.x - MROWS;
        float xv = cond[(size_t)bi*256 + t];
        float2 r = blockReduce2(xv, xv*xv, sh);
        float m = r.x * (1.0f/256.0f);
        float var = r.y * (1.0f/256.0f) - m*m;
        float rs = rsqrtf(var + 1e-5f);
        s_ln[t] = (xv - m)*rs*slng[t] + slnb[t];
        __syncthreads();
        float acc = 0.f;
        for (int c = 0; c < 256; c++) acc += s_ln[c] * g_wqt[c*256 + t];
        g_q[(size_t)bi*256 + t] = acc;
    }
}

// ---------------- k|v projection GEMM via mma.sync bf16, 3-stage cp.async ring ----
__device__ __forceinline__ void gemm_load_stage(int tid, int m0, int bn0, int ks, uint32_t sbase) {
    int kk = ks * GBK;
    int ka = (kk < 768) ? kk : kk - 768;
    uint32_t sA = sbase;
    uint32_t sB = sbase + 16384;
    #pragma unroll
    for (int i = 0; i < 4; i++) {
        int c = tid + i*256;
        int row = c >> 3, seg = c & 7;
        const char* src = (const char*)g_a2 + ((size_t)(m0+row)*1536 + ka)*2 + seg*16;
        CP16(sA + SWZ128((uint32_t)(row*128 + seg*16)), src);
    }
    #pragma unroll
    for (int i = 0; i < 4; i++) {
        int c = tid + i*256;
        int row = c >> 3, seg = c & 7;
        const char* src = (const char*)g_b2 + ((size_t)(bn0+row)*KEFF + kk)*2 + seg*16;
        CP16(sB + SWZ128((uint32_t)(row*128 + seg*16)), src);
    }
}

__global__ __launch_bounds__(256, 2) void gemm_kv_mma() {
    extern __shared__ char dynsm[];
    uint32_t sbase = (smem_u32(dynsm) + 1023u) & ~1023u;
    const int tid = threadIdx.x;
    const int wid = tid >> 5, lane = tid & 31;
    const int m0  = blockIdx.y * GBM;
    const int bn0 = blockIdx.x * GBN;
    const int wm = wid >> 1, wn = wid & 1;

    float acc[2][8][4];
    #pragma unroll
    for (int a = 0; a < 2; a++)
        #pragma unroll
        for (int b = 0; b < 8; b++)
            #pragma unroll
            for (int c = 0; c < 4; c++) acc[a][b][c] = 0.f;

    gemm_load_stage(tid, m0, bn0, 0, sbase);
    CP_COMMIT();
    gemm_load_stage(tid, m0, bn0, 1, sbase + GEMM_STAGE_BYTES);
    CP_COMMIT();

    const int a_row = wm*32 + (lane & 15);
    const int a_col = (lane >> 4) << 4;
    const int b_g = lane >> 3, b_r = lane & 7;
    const int b_row_in = ((b_g >> 1) << 3) + b_r;
    const int b_col = (b_g & 1) << 4;

    int cur = 0;  // buffer index of stage ks
    for (int ks = 0; ks < KSTAGES; ks++) {
        if (ks + 1 < KSTAGES) { CP_WAITG(1); } else { CP_WAITG(0); }
        __syncthreads();
        if (ks + 2 < KSTAGES) {
            int nxt = cur + 2; if (nxt >= 3) nxt -= 3;
            gemm_load_stage(tid, m0, bn0, ks + 2, sbase + nxt * GEMM_STAGE_BYTES);
            CP_COMMIT();
        }
        uint32_t sA = sbase + cur * GEMM_STAGE_BYTES;
        uint32_t sB = sA + 16384;
        #pragma unroll
        for (int k16 = 0; k16 < 4; k16++) {
            uint32_t afr[2][4], bfr[4][4];
            #pragma unroll
            for (int mt = 0; mt < 2; mt++) {
                uint32_t addr = sA + SWZ128((uint32_t)((a_row + mt*16)*128 + k16*32 + a_col));
                LDSM4(afr[mt], addr);
            }
            #pragma unroll
            for (int p = 0; p < 4; p++) {
                uint32_t addr = sB + SWZ128((uint32_t)((wn*64 + p*16 + b_row_in)*128 + k16*32 + b_col));
                LDSM4(bfr[p], addr);
            }
            #pragma unroll
            for (int mt = 0; mt < 2; mt++)
                #pragma unroll
                for (int nt = 0; nt < 8; nt++) {
                    int p = nt >> 1, h = nt & 1;
                    MMA16816(acc[mt][nt], afr[mt], bfr[p][h*2], bfr[p][h*2+1]);
                }
        }
        cur++; if (cur >= 3) cur = 0;
    }

    int quad = lane >> 2, qid = lane & 3;
    #pragma unroll
    for (int mt = 0; mt < 2; mt++)
        #pragma unroll
        for (int nt = 0; nt < 8; nt++) {
            int mrow = m0 + wm*32 + mt*16 + quad;
            int col  = bn0 + wn*64 + nt*8 + qid*2;
            *(float2*)(g_kv + (size_t)mrow*512 + col)     = make_float2(acc[mt][nt][0], acc[mt][nt][1]);
            *(float2*)(g_kv + (size_t)(mrow+8)*512 + col) = make_float2(acc[mt][nt][2], acc[mt][nt][3]);
        }
}

// ---------------- vsum ----------------
__global__ __launch_bounds__(256) void vsum_part_kernel() {
    int b = blockIdx.y, sp = blockIdx.x;
    int t = threadIdx.x;
    float s = 0.f;
    int j0 = sp * 256;
    for (int j = 0; j < 256; j++)
        s += g_kv[((size_t)(b*NTOK + j0 + j))*512 + 256 + t];
    g_vsp[(b*16+sp)*256 + t] = s;
}
__global__ __launch_bounds__(256) void vsum_reduce_kernel() {
    int b = blockIdx.x, t = threadIdx.x;
    float s = 0.f;
    for (int sp = 0; sp < 16; sp++) s += g_vsp[(b*16+sp)*256 + t];
    g_vsum[b*256 + t] = s;
}

// ---------------- slot LN + q projection (iters >= 1) ----------------
__global__ __launch_bounds__(256) void qproj_kernel(const float* __restrict__ lng,
                                                    const float* __restrict__ lnb) {
    __shared__ float s_ln[256];
    __shared__ float sh[16];
    int t = threadIdx.x;
    int bi = blockIdx.x;
    float xv = g_slots[(size_t)bi*256 + t];
    float2 r = blockReduce2(xv, xv*xv, sh);
    float m = r.x * (1.0f/256.0f);
    float var = r.y * (1.0f/256.0f) - m*m;
    float rs = rsqrtf(var + 1e-5f);
    s_ln[t] = (xv - m)*rs*lng[t] + lnb[t];
    __syncthreads();
    float acc = 0.f;
    for (int c = 0; c < 256; c++) acc += s_ln[c] * g_wqt[c*256 + t];
    g_q[(size_t)bi*256 + t] = acc;
}

// ---------------- attention pass (2 ch/thread, 8-float d-slices, 8-token softmax) -
__global__ __launch_bounds__(256, 3) void attn_kernel(float* __restrict__ attn_out, int lastIter) {
    extern __shared__ float dsm[];
    float* ksp  = dsm;                       // [TOKCH][384]
    float* vsp  = dsm + TOKCH*384;           // [TOKCH][384]
    float* wsum = dsm + 2*TOKCH*384;         // [8][9]
    float* tots = wsum + 8*9;                // [8] (stores reciprocals)

    int b = blockIdx.y, sp = blockIdx.x;
    int tid = threadIdx.x;
    int lane = tid & 31, wid = tid >> 5;
    int cg  = tid >> 3;          // channels cg and cg+32 (same head)
    int qd8 = tid & 7;
    int h   = cg & 3;
    int koff = (h*8 + qd8) * 12;

    float4 ql0, ql1, qh0, qh1;
    {
        const float* qp = g_q + (size_t)b*4096 + cg*64 + qd8*8;
        ql0 = *(const float4*)qp;        ql1 = *(const float4*)(qp + 4);
        qh0 = *(const float4*)(qp+2048); qh1 = *(const float4*)(qp + 2052);
    }

    float accA_lo[8] = {}, accA_hi[8] = {};
    float accS_lo = 0.f, accS_hi = 0.f;
    int j0base = sp * (NTOK/SPLITS);

    for (int ch = 0; ch < (NTOK/SPLITS)/TOKCH; ch++) {
        __syncthreads();
        int j0 = j0base + ch*TOKCH;
        #pragma unroll
        for (int it = 0; it < 8; it++) {
            int idx = tid + it*256;
            int r = idx >> 7, w4 = idx & 127;
            float4 v4 = *(const float4*)(g_kv + ((size_t)(b*NTOK + j0 + r))*512 + w4*4);
            int wl = w4 & 63;
            uint32_t off = r*384 + (wl >> 1)*12 + (wl & 1)*4;
            if (w4 < 64) *(float4*)&ksp[off] = v4;
            else         *(float4*)&vsp[off] = v4;
        }
        __syncthreads();

        #pragma unroll
        for (int g = 0; g < 2; g++) {
            int rbase = g*8;
            float e_lo[8], e_hi[8];
            #pragma unroll
            for (int r = 0; r < 8; r++) {
                const float* kp = &ksp[(rbase + r)*384 + koff];
                float4 k0 = *(const float4*)kp;
                float4 k1 = *(const float4*)(kp + 4);
                float pl = ql0.x*k0.x + ql0.y*k0.y + ql0.z*k0.z + ql0.w*k0.w
                         + ql1.x*k1.x + ql1.y*k1.y + ql1.z*k1.z + ql1.w*k1.w;
                float ph = qh0.x*k0.x + qh0.y*k0.y + qh0.z*k0.z + qh0.w*k0.w
                         + qh1.x*k1.x + qh1.y*k1.y + qh1.z*k1.z + qh1.w*k1.w;
                pl += __shfl_xor_sync(0xffffffffu, pl, 1);
                ph += __shfl_xor_sync(0xffffffffu, ph, 1);
                pl += __shfl_xor_sync(0xffffffffu, pl, 2);
                ph += __shfl_xor_sync(0xffffffffu, ph, 2);
                pl += __shfl_xor_sync(0xffffffffu, pl, 4);
                ph += __shfl_xor_sync(0xffffffffu, ph, 4);
                float el = __expf(pl * SCALE);
                float eh = __expf(ph * SCALE);
                e_lo[r] = el; e_hi[r] = eh;
                float cs = el + eh;
                cs += __shfl_xor_sync(0xffffffffu, cs, 8);
                cs += __shfl_xor_sync(0xffffffffu, cs, 16);
                if (lane == 0) wsum[wid*9 + r] = cs;
            }
            __syncthreads();
            if (tid < 64) {
                int rr = tid >> 3, ww = tid & 7;
                float vsm = wsum[ww*9 + rr];
                vsm += __shfl_xor_sync(0xffffffffu, vsm, 1);
                vsm += __shfl_xor_sync(0xffffffffu, vsm, 2);
                vsm += __shfl_xor_sync(0xffffffffu, vsm, 4);
                if (ww == 0) tots[rr] = rcp_fast(vsm);
            }
            __syncthreads();
            #pragma unroll
            for (int r = 0; r < 8; r++) {
                float rt = tots[r];
                float alo = e_lo[r] * rt;
                float ahi = e_hi[r] * rt;
                accS_lo += alo; accS_hi += ahi;
                const float* vp = &vsp[(rbase + r)*384 + koff];
                float4 v0 = *(const float4*)vp;
                float4 v1 = *(const float4*)(vp + 4);
                accA_lo[0] += alo*v0.x; accA_lo[1] += alo*v0.y; accA_lo[2] += alo*v0.z; accA_lo[3] += alo*v0.w;
                accA_lo[4] += alo*v1.x; accA_lo[5] += alo*v1.y; accA_lo[6] += alo*v1.z; accA_lo[7] += alo*v1.w;
                accA_hi[0] += ahi*v0.x; accA_hi[1] += ahi*v0.y; accA_hi[2] += ahi*v0.z; accA_hi[3] += ahi*v0.w;
                accA_hi[4] += ahi*v1.x; accA_hi[5] += ahi*v1.y; accA_hi[6] += ahi*v1.z; accA_hi[7] += ahi*v1.w;
                if (lastIter) {
                    float aol = alo + __shfl_xor_sync(0xffffffffu, alo, 8);
                    float aoh = ahi + __shfl_xor_sync(0xffffffffu, ahi, 8);
                    aol += __shfl_xor_sync(0xffffffffu, aol, 16);
                    aoh += __shfl_xor_sync(0xffffffffu, aoh, 16);
                    if (lane == 0) {
                        attn_out[((size_t)(b*KSLOT + wid))*NTOK + j0 + rbase + r]     = aol * 0.25f;
                        attn_out[((size_t)(b*KSLOT + wid + 8))*NTOK + j0 + rbase + r] = aoh * 0.25f;
                    }
                }
            }
        }
    }
    size_t base_lo = ((size_t)((b*SPLITS + sp)*CHAN + cg))*DH + qd8*8;
    size_t base_hi = ((size_t)((b*SPLITS + sp)*CHAN + cg + 32))*DH + qd8*8;
    *(float4*)(g_Apart + base_lo)     = make_float4(accA_lo[0], accA_lo[1], accA_lo[2], accA_lo[3]);
    *(float4*)(g_Apart + base_lo + 4) = make_float4(accA_lo[4], accA_lo[5], accA_lo[6], accA_lo[7]);
    *(float4*)(g_Apart + base_hi)     = make_float4(accA_hi[0], accA_hi[1], accA_hi[2], accA_hi[3]);
    *(float4*)(g_Apart + base_hi + 4) = make_float4(accA_hi[4], accA_hi[5], accA_hi[6], accA_hi[7]);
    if (qd8 == 0) {
        g_Spart[(b*SPLITS + sp)*CHAN + cg]      = accS_lo;
        g_Spart[(b*SPLITS + sp)*CHAN + cg + 32] = accS_hi;
    }
}

// ---------------- update: normalize + GRU + FF, 4 slots per block ----------------
__global__ __launch_bounds__(256) void update_kernel(
        const float* __restrict__ gbih, const float* __restrict__ gbhh,
        const float* __restrict__ ffg, const float* __restrict__ ffb,
        const float* __restrict__ fb1, const float* __restrict__ fb2,
        float* __restrict__ out_slots, int last) {
    __shared__ float u4 [4][256];
    __shared__ float h4 [4][256];
    __shared__ float hn4[4][256];
    __shared__ float ln4[4][256];
    __shared__ float h1s[4][1024];
    __shared__ float sh[16];
    int t = threadIdx.x;
    int base = blockIdx.x * 4;
    int b = base >> 4;
    int hh = t >> 6, d = t & 63;
    float vsm = g_vsum[b*256 + t];
    #pragma unroll
    for (int s = 0; s < 4; s++) {
        int i = (base + s) & 15;
        int c = i*NHEAD + hh;
        float A = 0.f, S0 = 0.f;
        #pragma unroll
        for (int sp = 0; sp < SPLITS; sp++) {
            A  += g_Apart[((size_t)((b*SPLITS+sp)*CHAN + c))*DH + d];
            S0 += g_Spart[(b*SPLITS+sp)*CHAN + c];
        }
        float S = S0 + (float)NTOK * EPSW;
        u4[s][t] = (A + EPSW * vsm) / S;
        h4[s][t] = g_slots[(size_t)(base+s)*256 + t];
    }
    __syncthreads();
    float gir[4] = {}, giz[4] = {}, gin[4] = {};
    float ghr[4] = {}, ghz[4] = {}, ghn[4] = {};
    for (int cc = 0; cc < 256; cc++) {
        float wr = g_wih_t[cc*768 + t];
        float wz = g_wih_t[cc*768 + 256 + t];
        float wn = g_wih_t[cc*768 + 512 + t];
        float vr = g_whh_t[cc*768 + t];
        float vz = g_whh_t[cc*768 + 256 + t];
        float vn = g_whh_t[cc*768 + 512 + t];
        #pragma unroll
        for (int s = 0; s < 4; s++) {
            float xv = u4[s][cc], hv = h4[s][cc];
            gir[s] += wr*xv; giz[s] += wz*xv; gin[s] += wn*xv;
            ghr[s] += vr*hv; ghz[s] += vz*hv; ghn[s] += vn*hv;
        }
    }
    float bir = gbih[t], biz = gbih[256+t], bin = gbih[512+t];
    float bhr = gbhh[t], bhz = gbhh[256+t], bhn = gbhh[512+t];
    #pragma unroll
    for (int s = 0; s < 4; s++) {
        float r = sigmoidf_(gir[s] + bir + ghr[s] + bhr);
        float z = sigmoidf_(giz[s] + biz + ghz[s] + bhz);
        float n = tanhf(gin[s] + bin + r*(ghn[s] + bhn));
        hn4[s][t] = (1.0f - z)*n + z*h4[s][t];
    }
    __syncthreads();
    #pragma unroll
    for (int s = 0; s < 4; s++) {
        float v = hn4[s][t];
        float2 r = blockReduce2(v, v*v, sh);
        float m = r.x * (1.0f/256.0f);
        float var = r.y * (1.0f/256.0f) - m*m;
        float rs = rsqrtf(var + 1e-5f);
        ln4[s][t] = (v - m)*rs*ffg[t] + ffb[t];
    }
    __syncthreads();
    float a1[4][4] = {};
    for (int cc = 0; cc < 256; cc++) {
        float w0 = g_wf1t[cc*1024 + t];
        float w1 = g_wf1t[cc*1024 + 256 + t];
        float w2 = g_wf1t[cc*1024 + 512 + t];
        float w3 = g_wf1t[cc*1024 + 768 + t];
        #pragma unroll
        for (int s = 0; s < 4; s++) {
            float xv = ln4[s][cc];
            a1[s][0] += w0*xv; a1[s][1] += w1*xv; a1[s][2] += w2*xv; a1[s][3] += w3*xv;
        }
    }
    #pragma unroll
    for (int s = 0; s < 4; s++) {
        #pragma unroll
        for (int q = 0; q < 4; q++) {
            int row = q*256 + t;
            h1s[s][row] = gelu_exact(a1[s][q] + fb1[row]);
        }
    }
    __syncthreads();
    float o[4];
    #pragma unroll
    for (int s = 0; s < 4; s++) o[s] = hn4[s][t] + fb2[t];
    for (int j = 0; j < 1024; j++) {
        float w = g_wf2t[j*256 + t];
        #pragma unroll
        for (int s = 0; s < 4; s++) o[s] += w * h1s[s][j];
    }
    #pragma unroll
    for (int s = 0; s < 4; s++) {
        g_slots[(size_t)(base+s)*256 + t] = o[s];
        if (last) out_slots[(size_t)(base+s)*256 + t] = o[s];
    }
}

// ---------------- launch ----------------
extern "C" void kernel_launch(void* const* d_in, const int* in_sizes, int n_in,
                              void* d_out, int out_size) {
    const float* inputs   = (const float*)d_in[0];
    const float* cond     = (const float*)d_in[1];
    const float* to_q_w   = (const float*)d_in[2];
    const float* to_k_w   = (const float*)d_in[3];
    const float* to_v_w   = (const float*)d_in[4];
    const float* gru_w_ih = (const float*)d_in[5];
    const float* gru_w_hh = (const float*)d_in[6];
    const float* gru_b_ih = (const float*)d_in[7];
    const float* gru_b_hh = (const float*)d_in[8];
    const float* ln_in_g  = (const float*)d_in[9];
    const float* ln_in_b  = (const float*)d_in[10];
    const float* ln_sl_g  = (const float*)d_in[11];
    const float* ln_sl_b  = (const float*)d_in[12];
    const float* ff_ln_g  = (const float*)d_in[13];
    const float* ff_ln_b  = (const float*)d_in[14];
    const float* ff_w1    = (const float*)d_in[15];
    const float* ff_b1    = (const float*)d_in[16];
    const float* ff_w2    = (const float*)d_in[17];
    const float* ff_b2    = (const float*)d_in[18];
    float* out = (float*)d_out;
    float* out_attn = out + BATCH*KSLOT*256;   // slots first, then attn_out

    cudaFuncSetAttribute(gemm_kv_mma, cudaFuncAttributeMaxDynamicSharedMemorySize, GEMM_DSMEM);
    cudaFuncSetAttribute(attn_kernel, cudaFuncAttributeMaxDynamicSharedMemorySize, ATTN_DSMEM);

    prep_kernel<<<1024, 256>>>(to_k_w, to_v_w, gru_w_ih, gru_w_hh, ff_w1, ff_w2, to_q_w, cond); // 0
    lnq_kernel<<<MROWS + BATCH*KSLOT, 256>>>(inputs, ln_in_g, ln_in_b, cond, ln_sl_g, ln_sl_b); // 1
    gemm_kv_mma<<<dim3(512/GBN, MROWS/GBM), 256, GEMM_DSMEM>>>();                               // 2
    attn_kernel<<<dim3(SPLITS, BATCH), 256, ATTN_DSMEM>>>(out_attn, 0);                         // 3 (ncu slot)
    vsum_part_kernel<<<dim3(16, BATCH), 256>>>();                                               // 4
    vsum_reduce_kernel<<<BATCH, 256>>>();                                                       // 5
    update_kernel<<<BATCH*KSLOT/4, 256>>>(gru_b_ih, gru_b_hh, ff_ln_g, ff_ln_b,
                                          ff_b1, ff_b2, out, 0);                                // 6

    for (int it = 1; it < ITERS; it++) {
        int last = (it == ITERS - 1) ? 1 : 0;
        qproj_kernel<<<BATCH*KSLOT, 256>>>(ln_sl_g, ln_sl_b);
        attn_kernel<<<dim3(SPLITS, BATCH), 256, ATTN_DSMEM>>>(out_attn, last);
        update_kernel<<<BATCH*KSLOT/4, 256>>>(gru_b_ih, gru_b_hh, ff_ln_g, ff_ln_b,
                                              ff_b1, ff_b2, out, last);
    }
}

// round 15
// speedup vs baseline: 2.0364x; 1.0607x over previous
#include <cuda_runtime.h>
#include <cuda_bf16.h>
#include <cstdint>

// ---------------- problem constants ----------------
#define BATCH 32
#define NTOK  4096
#define FEAT  768
#define DIM   256
#define KVQ   256
#define NHEAD 4
#define DH    64
#define KSLOT 16
#define CHAN  64            // KSLOT * NHEAD
#define ITERS 3
#define EPSW  1e-8f
#define SCALE 0.125f        // DH^-0.5
#define MROWS (BATCH*NTOK)  // 131072
#define SPLITS 32           // attention N-splits (tokens per block = 128)
#define TOKCH 16            // tokens per attention smem tile

// GEMM config (mma.sync bf16, 3-term split via K-concat)
#define GBM 128
#define GBN 128
#define GBK 64
#define KEFF 2304
#define KSTAGES (KEFF/GBK)  // 36
#define GEMM_STAGE_BYTES 32768
#define GEMM_DSMEM (3*GEMM_STAGE_BYTES + 1024)   // 3-stage ring

// attn dynamic smem: ks 16*384 + vs 16*384 + wsum 8*9 + tots 8
#define ATTN_SM_FLOATS (2*TOKCH*384 + 8*9 + 8)
#define ATTN_DSMEM (ATTN_SM_FLOATS*4)

// ---------------- scratch (device globals; no allocation allowed) ----------------
__device__ __align__(16) __nv_bfloat16 g_a2[(size_t)MROWS*1536]; // [m][hi|lo]
__device__ __align__(16) __nv_bfloat16 g_b2[512*KEFF];           // [n][hi|lo|hi]
__device__ float g_wqt [256*256];            // fp32
// fp32 weights packed as float2 for wide loads (exact):
__device__ float2 g_wgru2[256*768];          // [cc][j][t]: j0=(wr,wz) j1=(wn,vr) j2=(vz,vn)
__device__ float2 g_wf1v [256*512];          // [cc][j][t]: j0=(w0,w1) j1=(w2,w3)
__device__ float2 g_wf2v [512*256];          // [j2][t]: (w_{2j2}, w_{2j2+1})
__device__ float g_kv  [(size_t)MROWS*512];  // per token: k[0:256] | v[256:512]
__device__ float g_q   [BATCH*KSLOT*256];
__device__ float g_slots[BATCH*KSLOT*256];
__device__ float g_vsp [BATCH*16*256];
__device__ float g_vsum[BATCH*256];
__device__ float g_Apart[BATCH*SPLITS*CHAN*DH];
__device__ float g_Spart[BATCH*SPLITS*CHAN];

// ---------------- PTX helpers ----------------
__device__ __forceinline__ uint32_t smem_u32(const void* p) {
    uint32_t a;
    asm("{ .reg .u64 t; cvta.to.shared.u64 t, %1; cvt.u32.u64 %0, t; }" : "=r"(a) : "l"(p));
    return a;
}
#define SWZ128(off) ((off) ^ (((off) >> 3) & 0x70))
#define CP16(dst, src) asm volatile("cp.async.cg.shared.global [%0], [%1], 16;" :: "r"(dst), "l"(src))
#define CP_COMMIT()    asm volatile("cp.async.commit_group;" ::: "memory")
#define CP_WAITG(n)    asm volatile("cp.async.wait_group %0;" :: "n"(n) : "memory")

#define LDSM4(R, addr) \
  asm volatile("ldmatrix.sync.aligned.m8n8.x4.shared.b16 {%0,%1,%2,%3}, [%4];" \
    : "=r"((R)[0]), "=r"((R)[1]), "=r"((R)[2]), "=r"((R)[3]) : "r"(addr))

#define MMA16816(C, A, B0, B1) \
  asm volatile("mma.sync.aligned.m16n8k16.row.col.f32.bf16.bf16.f32 " \
    "{%0,%1,%2,%3}, {%4,%5,%6,%7}, {%8,%9}, {%0,%1,%2,%3};" \
    : "+f"((C)[0]), "+f"((C)[1]), "+f"((C)[2]), "+f"((C)[3]) \
    : "r"((A)[0]), "r"((A)[1]), "r"((A)[2]), "r"((A)[3]), "r"(B0), "r"(B1))

// ---------------- generic helpers ----------------
__device__ __forceinline__ float2 blockReduce2(float a, float b, float* sh) {
    __syncthreads();
    #pragma unroll
    for (int off = 16; off; off >>= 1) {
        a += __shfl_xor_sync(0xffffffffu, a, off);
        b += __shfl_xor_sync(0xffffffffu, b, off);
    }
    int wid = threadIdx.x >> 5, lane = threadIdx.x & 31;
    if (lane == 0) { sh[wid*2] = a; sh[wid*2+1] = b; }
    __syncthreads();
    float ra = 0.f, rb = 0.f;
    #pragma unroll
    for (int w = 0; w < 8; w++) { ra += sh[w*2]; rb += sh[w*2+1]; }
    return make_float2(ra, rb);
}
__device__ __forceinline__ float sigmoidf_(float x) { return 1.0f / (1.0f + __expf(-x)); }
__device__ __forceinline__ float gelu_exact(float x) { return 0.5f * x * (1.0f + erff(x * 0.70710678118654752f)); }
__device__ __forceinline__ float rcp_fast(float x) { float r; asm("rcp.approx.f32 %0, %1;" : "=f"(r) : "f"(x)); return r; }

// ---------------- prep A: split-bf16 B for the kv GEMM ----------------
__global__ void prep_a_kernel(const float* __restrict__ kw, const float* __restrict__ vw) {
    int idx = blockIdx.x * blockDim.x + threadIdx.x;
    int stride = gridDim.x * blockDim.x;
    for (int p = idx; p < 512*KEFF; p += stride) {
        int n = p / KEFF, kk = p - n*KEFF;
        int k = (kk < 768) ? kk : ((kk < 1536) ? kk - 768 : kk - 1536);
        float src = (n < 256) ? kw[n*768 + k] : vw[(n-256)*768 + k];
        __nv_bfloat16 h = __float2bfloat16(src);
        if (kk >= 768 && kk < 1536) h = __float2bfloat16(src - __bfloat162float(h));
        g_b2[p] = h;
    }
}

// ---------------- prep B: float2-packed fp32 update weights + wqt + slots --------
__global__ void prep_b_kernel(const float* __restrict__ wih, const float* __restrict__ whh,
                              const float* __restrict__ f1, const float* __restrict__ f2,
                              const float* __restrict__ qw, const float* __restrict__ cond) {
    int idx = blockIdx.x * blockDim.x + threadIdx.x;
    int stride = gridDim.x * blockDim.x;
    for (int p = idx; p < 256*768; p += stride) {
        int cc = p / 768, rem = p - cc*768;
        int j = rem >> 8, t = rem & 255;
        float2 u;
        if (j == 0)      u = make_float2(wih[t*256 + cc],       wih[(256+t)*256 + cc]);
        else if (j == 1) u = make_float2(wih[(512+t)*256 + cc], whh[t*256 + cc]);
        else             u = make_float2(whh[(256+t)*256 + cc], whh[(512+t)*256 + cc]);
        g_wgru2[p] = u;
    }
    for (int p = idx; p < 256*512; p += stride) {
        int cc = p >> 9, rem = p & 511;
        int j = rem >> 8, t = rem & 255;
        float2 u = (j == 0) ? make_float2(f1[t*256 + cc],       f1[(256+t)*256 + cc])
                            : make_float2(f1[(512+t)*256 + cc], f1[(768+t)*256 + cc]);
        g_wf1v[p] = u;
    }
    for (int p = idx; p < 512*256; p += stride) {
        int j2 = p >> 8, t = p & 255;
        g_wf2v[p] = make_float2(f2[t*1024 + 2*j2], f2[t*1024 + 2*j2 + 1]);
    }
    for (int p = idx; p < 256*256; p += stride)  g_wqt[p] = qw[(p & 255)*256 + (p >> 8)];
    for (int p = idx; p < BATCH*KSLOT*256; p += stride) g_slots[p] = cond[p];
}

// ---------------- fused input LN+convert AND iter-0 qproj ----------------
__global__ __launch_bounds__(256) void lnq_kernel(const float* __restrict__ x,
                                                  const float* __restrict__ lng,
                                                  const float* __restrict__ lnb,
                                                  const float* __restrict__ cond,
                                                  const float* __restrict__ slng,
                                                  const float* __restrict__ slnb) {
    __shared__ float sh[16];
    __shared__ float s_ln[256];
    int t = threadIdx.x;
    if (blockIdx.x < MROWS) {
        size_t row = blockIdx.x;
        const float* xr = x + row * FEAT;
        float v0 = xr[t], v1 = xr[t+256], v2 = xr[t+512];
        float2 r = blockReduce2(v0+v1+v2, v0*v0 + v1*v1 + v2*v2, sh);
        float m = r.x * (1.0f/768.0f);
        float var = r.y * (1.0f/768.0f) - m*m;
        float rs = rsqrtf(var + 1e-5f);
        __nv_bfloat16* dst = g_a2 + row * 1536;
        float vv[3] = {v0, v1, v2};
        #pragma unroll
        for (int i = 0; i < 3; i++) {
            int col = t + i*256;
            float val = (vv[i] - m)*rs*lng[col] + lnb[col];
            __nv_bfloat16 hi = __float2bfloat16(val);
            __nv_bfloat16 lo = __float2bfloat16(val - __bfloat162float(hi));
            dst[col] = hi;
            dst[768 + col] = lo;
        }
    } else {
        int bi = blockIdx.x - MROWS;
        float xv = cond[(size_t)bi*256 + t];
        float2 r = blockReduce2(xv, xv*xv, sh);
        float m = r.x * (1.0f/256.0f);
        float var = r.y * (1.0f/256.0f) - m*m;
        float rs = rsqrtf(var + 1e-5f);
        s_ln[t] = (xv - m)*rs*slng[t] + slnb[t];
        __syncthreads();
        float acc = 0.f;
        for (int c = 0; c < 256; c++) acc += s_ln[c] * g_wqt[c*256 + t];
        g_q[(size_t)bi*256 + t] = acc;
    }
}

// ---------------- k|v projection GEMM via mma.sync bf16, 3-stage cp.async ring ----
__device__ __forceinline__ void gemm_load_stage(int tid, int m0, int bn0, int ks, uint32_t sbase) {
    int kk = ks * GBK;
    int ka = (kk < 768) ? kk : kk - 768;
    uint32_t sA = sbase;
    uint32_t sB = sbase + 16384;
    #pragma unroll
    for (int i = 0; i < 4; i++) {
        int c = tid + i*256;
        int row = c >> 3, seg = c & 7;
        const char* src = (const char*)g_a2 + ((size_t)(m0+row)*1536 + ka)*2 + seg*16;
        CP16(sA + SWZ128((uint32_t)(row*128 + seg*16)), src);
    }
    #pragma unroll
    for (int i = 0; i < 4; i++) {
        int c = tid + i*256;
        int row = c >> 3, seg = c & 7;
        const char* src = (const char*)g_b2 + ((size_t)(bn0+row)*KEFF + kk)*2 + seg*16;
        CP16(sB + SWZ128((uint32_t)(row*128 + seg*16)), src);
    }
}

__global__ __launch_bounds__(256, 2) void gemm_kv_mma() {
    extern __shared__ char dynsm[];
    uint32_t sbase = (smem_u32(dynsm) + 1023u) & ~1023u;
    const int tid = threadIdx.x;
    const int wid = tid >> 5, lane = tid & 31;
    const int m0  = blockIdx.y * GBM;
    const int bn0 = blockIdx.x * GBN;
    const int wm = wid >> 1, wn = wid & 1;

    float acc[2][8][4];
    #pragma unroll
    for (int a = 0; a < 2; a++)
        #pragma unroll
        for (int b = 0; b < 8; b++)
            #pragma unroll
            for (int c = 0; c < 4; c++) acc[a][b][c] = 0.f;

    gemm_load_stage(tid, m0, bn0, 0, sbase);
    CP_COMMIT();
    gemm_load_stage(tid, m0, bn0, 1, sbase + GEMM_STAGE_BYTES);
    CP_COMMIT();

    const int a_row = wm*32 + (lane & 15);
    const int a_col = (lane >> 4) << 4;
    const int b_g = lane >> 3, b_r = lane & 7;
    const int b_row_in = ((b_g >> 1) << 3) + b_r;
    const int b_col = (b_g & 1) << 4;

    int cur = 0;
    for (int ks = 0; ks < KSTAGES; ks++) {
        if (ks + 1 < KSTAGES) { CP_WAITG(1); } else { CP_WAITG(0); }
        __syncthreads();
        if (ks + 2 < KSTAGES) {
            int nxt = cur + 2; if (nxt >= 3) nxt -= 3;
            gemm_load_stage(tid, m0, bn0, ks + 2, sbase + nxt * GEMM_STAGE_BYTES);
            CP_COMMIT();
        }
        uint32_t sA = sbase + cur * GEMM_STAGE_BYTES;
        uint32_t sB = sA + 16384;
        #pragma unroll
        for (int k16 = 0; k16 < 4; k16++) {
            uint32_t afr[2][4], bfr[4][4];
            #pragma unroll
            for (int mt = 0; mt < 2; mt++) {
                uint32_t addr = sA + SWZ128((uint32_t)((a_row + mt*16)*128 + k16*32 + a_col));
                LDSM4(afr[mt], addr);
            }
            #pragma unroll
            for (int p = 0; p < 4; p++) {
                uint32_t addr = sB + SWZ128((uint32_t)((wn*64 + p*16 + b_row_in)*128 + k16*32 + b_col));
                LDSM4(bfr[p], addr);
            }
            #pragma unroll
            for (int mt = 0; mt < 2; mt++)
                #pragma unroll
                for (int nt = 0; nt < 8; nt++) {
                    int p = nt >> 1, h = nt & 1;
                    MMA16816(acc[mt][nt], afr[mt], bfr[p][h*2], bfr[p][h*2+1]);
                }
        }
        cur++; if (cur >= 3) cur = 0;
    }

    int quad = lane >> 2, qid = lane & 3;
    #pragma unroll
    for (int mt = 0; mt < 2; mt++)
        #pragma unroll
        for (int nt = 0; nt < 8; nt++) {
            int mrow = m0 + wm*32 + mt*16 + quad;
            int col  = bn0 + wn*64 + nt*8 + qid*2;
            *(float2*)(g_kv + (size_t)mrow*512 + col)     = make_float2(acc[mt][nt][0], acc[mt][nt][1]);
            *(float2*)(g_kv + (size_t)(mrow+8)*512 + col) = make_float2(acc[mt][nt][2], acc[mt][nt][3]);
        }
}

// ---------------- vsum ----------------
__global__ __launch_bounds__(256) void vsum_part_kernel() {
    int b = blockIdx.y, sp = blockIdx.x;
    int t = threadIdx.x;
    float s = 0.f;
    int j0 = sp * 256;
    for (int j = 0; j < 256; j++)
        s += g_kv[((size_t)(b*NTOK + j0 + j))*512 + 256 + t];
    g_vsp[(b*16+sp)*256 + t] = s;
}
__global__ __launch_bounds__(256) void vsum_reduce_kernel() {
    int b = blockIdx.x, t = threadIdx.x;
    float s = 0.f;
    for (int sp = 0; sp < 16; sp++) s += g_vsp[(b*16+sp)*256 + t];
    g_vsum[b*256 + t] = s;
}

// ---------------- slot LN + q projection (iters >= 1) ----------------
__global__ __launch_bounds__(256) void qproj_kernel(const float* __restrict__ lng,
                                                    const float* __restrict__ lnb) {
    __shared__ float s_ln[256];
    __shared__ float sh[16];
    int t = threadIdx.x;
    int bi = blockIdx.x;
    float xv = g_slots[(size_t)bi*256 + t];
    float2 r = blockReduce2(xv, xv*xv, sh);
    float m = r.x * (1.0f/256.0f);
    float var = r.y * (1.0f/256.0f) - m*m;
    float rs = rsqrtf(var + 1e-5f);
    s_ln[t] = (xv - m)*rs*lng[t] + lnb[t];
    __syncthreads();
    float acc = 0.f;
    for (int c = 0; c < 256; c++) acc += s_ln[c] * g_wqt[c*256 + t];
    g_q[(size_t)bi*256 + t] = acc;
}

// ---------------- attention pass (2 ch/thread, 8-float d-slices, 8-token softmax) -
__global__ __launch_bounds__(256, 3) void attn_kernel(float* __restrict__ attn_out, int lastIter) {
    extern __shared__ float dsm[];
    float* ksp  = dsm;
    float* vsp  = dsm + TOKCH*384;
    float* wsum = dsm + 2*TOKCH*384;
    float* tots = wsum + 8*9;

    int b = blockIdx.y, sp = blockIdx.x;
    int tid = threadIdx.x;
    int lane = tid & 31, wid = tid >> 5;
    int cg  = tid >> 3;
    int qd8 = tid & 7;
    int h   = cg & 3;
    int koff = (h*8 + qd8) * 12;

    // q pre-scaled by SCALE (folds softmax scale into the dot)
    float4 ql0, ql1, qh0, qh1;
    {
        const float* qp = g_q + (size_t)b*4096 + cg*64 + qd8*8;
        ql0 = *(const float4*)qp;        ql1 = *(const float4*)(qp + 4);
        qh0 = *(const float4*)(qp+2048); qh1 = *(const float4*)(qp + 2052);
        ql0.x*=SCALE; ql0.y*=SCALE; ql0.z*=SCALE; ql0.w*=SCALE;
        ql1.x*=SCALE; ql1.y*=SCALE; ql1.z*=SCALE; ql1.w*=SCALE;
        qh0.x*=SCALE; qh0.y*=SCALE; qh0.z*=SCALE; qh0.w*=SCALE;
        qh1.x*=SCALE; qh1.y*=SCALE; qh1.z*=SCALE; qh1.w*=SCALE;
    }

    float accA_lo[8] = {}, accA_hi[8] = {};
    float accS_lo = 0.f, accS_hi = 0.f;
    int j0base = sp * (NTOK/SPLITS);

    for (int ch = 0; ch < (NTOK/SPLITS)/TOKCH; ch++) {
        __syncthreads();
        int j0 = j0base + ch*TOKCH;
        #pragma unroll
        for (int it = 0; it < 8; it++) {
            int idx = tid + it*256;
            int r = idx >> 7, w4 = idx & 127;
            float4 v4 = *(const float4*)(g_kv + ((size_t)(b*NTOK + j0 + r))*512 + w4*4);
            int wl = w4 & 63;
            uint32_t off = r*384 + (wl >> 1)*12 + (wl & 1)*4;
            if (w4 < 64) *(float4*)&ksp[off] = v4;
            else         *(float4*)&vsp[off] = v4;
        }
        __syncthreads();

        #pragma unroll
        for (int g = 0; g < 2; g++) {
            int rbase = g*8;
            float e_lo[8], e_hi[8];
            #pragma unroll
            for (int r = 0; r < 8; r++) {
                const float* kp = &ksp[(rbase + r)*384 + koff];
                float4 k0 = *(const float4*)kp;
                float4 k1 = *(const float4*)(kp + 4);
                float pl = ql0.x*k0.x + ql0.y*k0.y + ql0.z*k0.z + ql0.w*k0.w
                         + ql1.x*k1.x + ql1.y*k1.y + ql1.z*k1.z + ql1.w*k1.w;
                float ph = qh0.x*k0.x + qh0.y*k0.y + qh0.z*k0.z + qh0.w*k0.w
                         + qh1.x*k1.x + qh1.y*k1.y + qh1.z*k1.z + qh1.w*k1.w;
                pl += __shfl_xor_sync(0xffffffffu, pl, 1);
                ph += __shfl_xor_sync(0xffffffffu, ph, 1);
                pl += __shfl_xor_sync(0xffffffffu, pl, 2);
                ph += __shfl_xor_sync(0xffffffffu, ph, 2);
                pl += __shfl_xor_sync(0xffffffffu, pl, 4);
                ph += __shfl_xor_sync(0xffffffffu, ph, 4);
                float el = __expf(pl);
                float eh = __expf(ph);
                e_lo[r] = el; e_hi[r] = eh;
                float cs = el + eh;
                cs += __shfl_xor_sync(0xffffffffu, cs, 8);
                cs += __shfl_xor_sync(0xffffffffu, cs, 16);
                if (lane == 0) wsum[wid*9 + r] = cs;
            }
            __syncthreads();
            if (tid < 64) {
                int rr = tid >> 3, ww = tid & 7;
                float vsm = wsum[ww*9 + rr];
                vsm += __shfl_xor_sync(0xffffffffu, vsm, 1);
                vsm += __shfl_xor_sync(0xffffffffu, vsm, 2);
                vsm += __shfl_xor_sync(0xffffffffu, vsm, 4);
                if (ww == 0) tots[rr] = rcp_fast(vsm);
            }
            __syncthreads();
            #pragma unroll
            for (int r = 0; r < 8; r++) {
                float rt = tots[r];
                float alo = e_lo[r] * rt;
                float ahi = e_hi[r] * rt;
                accS_lo += alo; accS_hi += ahi;
                const float* vp = &vsp[(rbase + r)*384 + koff];
                float4 v0 = *(const float4*)vp;
                float4 v1 = *(const float4*)(vp + 4);
                accA_lo[0] += alo*v0.x; accA_lo[1] += alo*v0.y; accA_lo[2] += alo*v0.z; accA_lo[3] += alo*v0.w;
                accA_lo[4] += alo*v1.x; accA_lo[5] += alo*v1.y; accA_lo[6] += alo*v1.z; accA_lo[7] += alo*v1.w;
                accA_hi[0] += ahi*v0.x; accA_hi[1] += ahi*v0.y; accA_hi[2] += ahi*v0.z; accA_hi[3] += ahi*v0.w;
                accA_hi[4] += ahi*v1.x; accA_hi[5] += ahi*v1.y; accA_hi[6] += ahi*v1.z; accA_hi[7] += ahi*v1.w;
                if (lastIter) {
                    float aol = alo + __shfl_xor_sync(0xffffffffu, alo, 8);
                    float aoh = ahi + __shfl_xor_sync(0xffffffffu, ahi, 8);
                    aol += __shfl_xor_sync(0xffffffffu, aol, 16);
                    aoh += __shfl_xor_sync(0xffffffffu, aoh, 16);
                    if (lane == 0) {
                        attn_out[((size_t)(b*KSLOT + wid))*NTOK + j0 + rbase + r]     = aol * 0.25f;
                        attn_out[((size_t)(b*KSLOT + wid + 8))*NTOK + j0 + rbase + r] = aoh * 0.25f;
                    }
                }
            }
        }
    }
    size_t base_lo = ((size_t)((b*SPLITS + sp)*CHAN + cg))*DH + qd8*8;
    size_t base_hi = ((size_t)((b*SPLITS + sp)*CHAN + cg + 32))*DH + qd8*8;
    *(float4*)(g_Apart + base_lo)     = make_float4(accA_lo[0], accA_lo[1], accA_lo[2], accA_lo[3]);
    *(float4*)(g_Apart + base_lo + 4) = make_float4(accA_lo[4], accA_lo[5], accA_lo[6], accA_lo[7]);
    *(float4*)(g_Apart + base_hi)     = make_float4(accA_hi[0], accA_hi[1], accA_hi[2], accA_hi[3]);
    *(float4*)(g_Apart + base_hi + 4) = make_float4(accA_hi[4], accA_hi[5], accA_hi[6], accA_hi[7]);
    if (qd8 == 0) {
        g_Spart[(b*SPLITS + sp)*CHAN + cg]      = accS_lo;
        g_Spart[(b*SPLITS + sp)*CHAN + cg + 32] = accS_hi;
    }
}

// ---------------- update: normalize + GRU + FF (fp32 float2-packed weights) -------
__global__ __launch_bounds__(256) void update_kernel(
        const float* __restrict__ gbih, const float* __restrict__ gbhh,
        const float* __restrict__ ffg, const float* __restrict__ ffb,
        const float* __restrict__ fb1, const float* __restrict__ fb2,
        float* __restrict__ out_slots, int last) {
    __shared__ float u4 [4][256];
    __shared__ float h4 [4][256];
    __shared__ float hn4[4][256];
    __shared__ float ln4[4][256];
    __shared__ float h1s[4][1024];
    __shared__ float sh[16];
    int t = threadIdx.x;
    int base = blockIdx.x * 4;
    int b = base >> 4;
    int hh = t >> 6, d = t & 63;
    float vsm = g_vsum[b*256 + t];
    #pragma unroll
    for (int s = 0; s < 4; s++) {
        int i = (base + s) & 15;
        int c = i*NHEAD + hh;
        float A = 0.f, S0 = 0.f;
        #pragma unroll
        for (int sp = 0; sp < SPLITS; sp++) {
            A  += g_Apart[((size_t)((b*SPLITS+sp)*CHAN + c))*DH + d];
            S0 += g_Spart[(b*SPLITS+sp)*CHAN + c];
        }
        float S = S0 + (float)NTOK * EPSW;
        u4[s][t] = (A + EPSW * vsm) / S;
        h4[s][t] = g_slots[(size_t)(base+s)*256 + t];
    }
    __syncthreads();
    float gir[4] = {}, giz[4] = {}, gin[4] = {};
    float ghr[4] = {}, ghz[4] = {}, ghn[4] = {};
    for (int cc = 0; cc < 256; cc++) {
        float2 p0 = g_wgru2[cc*768 + t];
        float2 p1 = g_wgru2[cc*768 + 256 + t];
        float2 p2 = g_wgru2[cc*768 + 512 + t];
        float wr = p0.x, wz = p0.y;
        float wn = p1.x, vr = p1.y;
        float vz = p2.x, vn = p2.y;
        #pragma unroll
        for (int s = 0; s < 4; s++) {
            float xv = u4[s][cc], hv = h4[s][cc];
            gir[s] += wr*xv; giz[s] += wz*xv; gin[s] += wn*xv;
            ghr[s] += vr*hv; ghz[s] += vz*hv; ghn[s] += vn*hv;
        }
    }
    float bir = gbih[t], biz = gbih[256+t], bin = gbih[512+t];
    float bhr = gbhh[t], bhz = gbhh[256+t], bhn = gbhh[512+t];
    #pragma unroll
    for (int s = 0; s < 4; s++) {
        float r = sigmoidf_(gir[s] + bir + ghr[s] + bhr);
        float z = sigmoidf_(giz[s] + biz + ghz[s] + bhz);
        float n = tanhf(gin[s] + bin + r*(ghn[s] + bhn));
        hn4[s][t] = (1.0f - z)*n + z*h4[s][t];
    }
    __syncthreads();
    #pragma unroll
    for (int s = 0; s < 4; s++) {
        float v = hn4[s][t];
        float2 r = blockReduce2(v, v*v, sh);
        float m = r.x * (1.0f/256.0f);
        float var = r.y * (1.0f/256.0f) - m*m;
        float rs = rsqrtf(var + 1e-5f);
        ln4[s][t] = (v - m)*rs*ffg[t] + ffb[t];
    }
    __syncthreads();
    float a1[4][4] = {};
    for (int cc = 0; cc < 256; cc++) {
        float2 p0 = g_wf1v[cc*512 + t];
        float2 p1 = g_wf1v[cc*512 + 256 + t];
        float w0 = p0.x, w1 = p0.y;
        float w2 = p1.x, w3 = p1.y;
        #pragma unroll
        for (int s = 0; s < 4; s++) {
            float xv = ln4[s][cc];
            a1[s][0] += w0*xv; a1[s][1] += w1*xv; a1[s][2] += w2*xv; a1[s][3] += w3*xv;
        }
    }
    #pragma unroll
    for (int s = 0; s < 4; s++) {
        #pragma unroll
        for (int q = 0; q < 4; q++) {
            int row = q*256 + t;
            h1s[s][row] = gelu_exact(a1[s][q] + fb1[row]);
        }
    }
    __syncthreads();
    float o[4];
    #pragma unroll
    for (int s = 0; s < 4; s++) o[s] = hn4[s][t] + fb2[t];
    for (int j2 = 0; j2 < 512; j2++) {
        float2 p = g_wf2v[j2*256 + t];
        #pragma unroll
        for (int s = 0; s < 4; s++)
            o[s] += p.x * h1s[s][2*j2] + p.y * h1s[s][2*j2 + 1];
    }
    #pragma unroll
    for (int s = 0; s < 4; s++) {
        g_slots[(size_t)(base+s)*256 + t] = o[s];
        if (last) out_slots[(size_t)(base+s)*256 + t] = o[s];
    }
}

// ---------------- launch ----------------
extern "C" void kernel_launch(void* const* d_in, const int* in_sizes, int n_in,
                              void* d_out, int out_size) {
    const float* inputs   = (const float*)d_in[0];
    const float* cond     = (const float*)d_in[1];
    const float* to_q_w   = (const float*)d_in[2];
    const float* to_k_w   = (const float*)d_in[3];
    const float* to_v_w   = (const float*)d_in[4];
    const float* gru_w_ih = (const float*)d_in[5];
    const float* gru_w_hh = (const float*)d_in[6];
    const float* gru_b_ih = (const float*)d_in[7];
    const float* gru_b_hh = (const float*)d_in[8];
    const float* ln_in_g  = (const float*)d_in[9];
    const float* ln_in_b  = (const float*)d_in[10];
    const float* ln_sl_g  = (const float*)d_in[11];
    const float* ln_sl_b  = (const float*)d_in[12];
    const float* ff_ln_g  = (const float*)d_in[13];
    const float* ff_ln_b  = (const float*)d_in[14];
    const float* ff_w1    = (const float*)d_in[15];
    const float* ff_b1    = (const float*)d_in[16];
    const float* ff_w2    = (const float*)d_in[17];
    const float* ff_b2    = (const float*)d_in[18];
    float* out = (float*)d_out;
    float* out_attn = out + BATCH*KSLOT*256;   // slots first, then attn_out

    cudaFuncSetAttribute(gemm_kv_mma, cudaFuncAttributeMaxDynamicSharedMemorySize, GEMM_DSMEM);
    cudaFuncSetAttribute(attn_kernel, cudaFuncAttributeMaxDynamicSharedMemorySize, ATTN_DSMEM);

    prep_a_kernel<<<1024, 256>>>(to_k_w, to_v_w);                                               // 0
    prep_b_kernel<<<512, 256>>>(gru_w_ih, gru_w_hh, ff_w1, ff_w2, to_q_w, cond);                // 1
    lnq_kernel<<<MROWS + BATCH*KSLOT, 256>>>(inputs, ln_in_g, ln_in_b, cond, ln_sl_g, ln_sl_b); // 2
    gemm_kv_mma<<<dim3(512/GBN, MROWS/GBM), 256, GEMM_DSMEM>>>();                               // 3 (ncu slot)
    attn_kernel<<<dim3(SPLITS, BATCH), 256, ATTN_DSMEM>>>(out_attn, 0);                         // 4
    vsum_part_kernel<<<dim3(16, BATCH), 256>>>();                                               // 5
    vsum_reduce_kernel<<<BATCH, 256>>>();                                                       // 6
    update_kernel<<<BATCH*KSLOT/4, 256>>>(gru_b_ih, gru_b_hh, ff_ln_g, ff_ln_b,
                                          ff_b1, ff_b2, out, 0);                                // 7

    for (int it = 1; it < ITERS; it++) {
        int last = (it == ITERS - 1) ? 1 : 0;
        qproj_kernel<<<BATCH*KSLOT, 256>>>(ln_sl_g, ln_sl_b);
        attn_kernel<<<dim3(SPLITS, BATCH), 256, ATTN_DSMEM>>>(out_attn, last);
        update_kernel<<<BATCH*KSLOT/4, 256>>>(gru_b_ih, gru_b_hh, ff_ln_g, ff_ln_b,
                                              ff_b1, ff_b2, out, last);
    }
}